// round 1
// baseline (speedup 1.0000x reference)
#include <cuda_runtime.h>

#define NN 20000
#define EE 320000
#define FF 128
#define D0 256
#define D1 512
#define HH 2
#define CC 256
#define GG 128
#define NC 10

// ---------------- scratch (device globals; no allocation allowed) ----------------
__device__ float g_h1[NN * D0];
__device__ float g_h2[NN * D0];
__device__ float g_xw[NN * D1];
__device__ float g_h3[NN * D1];
__device__ float g_h4[NN * D1];
__device__ float g_ls[NN * HH];
__device__ float g_ld[NN * HH];
__device__ int   g_deg[NN];
__device__ int   g_off[NN + 1];
__device__ int   g_cur[NN];
__device__ int   g_csr[EE];
__device__ int   g_bsum[64];
__device__ float g_sc1[D0], g_sh1[D0], g_sc2[D0], g_sh2[D0];
__device__ float g_pool[GG * D1];
__device__ float g_cnt[GG];

// ---------------- zero per-call state ----------------
__global__ void zero_kernel() {
    int i = blockIdx.x * blockDim.x + threadIdx.x;
    if (i < GG * D1) g_pool[i] = 0.f;
    if (i < NN) g_deg[i] = 0;
    if (i < GG) g_cnt[i] = 0.f;
}

// ---------------- fold BN (eval) + linear bias into scale/shift ----------------
__global__ void prep_bn(const float* lb1, const float* g1, const float* b1,
                        const float* m1, const float* v1,
                        const float* lb2, const float* g2, const float* b2,
                        const float* m2, const float* v2) {
    int t = threadIdx.x;
    if (t < D0) {
        float sc = g1[t] * rsqrtf(v1[t] + 1e-5f);
        g_sc1[t] = sc;
        g_sh1[t] = (lb1[t] - m1[t]) * sc + b1[t];
        float sc2 = g2[t] * rsqrtf(v2[t] + 1e-5f);
        g_sc2[t] = sc2;
        g_sh2[t] = (lb2[t] - m2[t]) * sc2 + b2[t];
    }
}

// ---------------- SIMT fp32 GEMM: C[M,N] = A[M,K] @ B[K,N] ----------------
// EPI==0: plain store. EPI==1: relu(acc*scale[n] + shift[n])
template <int EPI>
__global__ void __launch_bounds__(256) sgemm(
    const float* __restrict__ A, const float* __restrict__ B,
    float* __restrict__ Cm, int M, int Nn, int K,
    const float* __restrict__ scale, const float* __restrict__ shift)
{
    const int BM = 128, BN = 128, BK = 16;
    __shared__ float As[BK][BM];
    __shared__ float Bs[BK][BN];
    int tid = threadIdx.x;
    int tx = tid & 15, ty = tid >> 4;
    int m0 = blockIdx.y * BM, n0 = blockIdx.x * BN;
    float acc[8][8] = {};
    for (int k0 = 0; k0 < K; k0 += BK) {
        // A tile: 128x16, transposed into As[k][m]
#pragma unroll
        for (int l = 0; l < 2; l++) {
            int t2 = tid + l * 256;
            int row = t2 >> 2;
            int col = (t2 & 3) * 4;
            float4 av = make_float4(0.f, 0.f, 0.f, 0.f);
            if (m0 + row < M)
                av = *(const float4*)(A + (size_t)(m0 + row) * K + k0 + col);
            As[col + 0][row] = av.x; As[col + 1][row] = av.y;
            As[col + 2][row] = av.z; As[col + 3][row] = av.w;
        }
        // B tile: 16x128
#pragma unroll
        for (int l = 0; l < 2; l++) {
            int t2 = tid + l * 256;
            int row = t2 >> 5;
            int col = (t2 & 31) * 4;
            *(float4*)(&Bs[row][col]) =
                *(const float4*)(B + (size_t)(k0 + row) * Nn + n0 + col);
        }
        __syncthreads();
#pragma unroll
        for (int kk = 0; kk < BK; kk++) {
            float ra[8], rb[8];
#pragma unroll
            for (int i = 0; i < 8; i++) ra[i] = As[kk][ty * 8 + i];
#pragma unroll
            for (int j = 0; j < 8; j++) rb[j] = Bs[kk][tx * 8 + j];
#pragma unroll
            for (int i = 0; i < 8; i++)
#pragma unroll
                for (int j = 0; j < 8; j++)
                    acc[i][j] += ra[i] * rb[j];
        }
        __syncthreads();
    }
#pragma unroll
    for (int i = 0; i < 8; i++) {
        int row = m0 + ty * 8 + i;
        if (row >= M) continue;
#pragma unroll
        for (int j = 0; j < 8; j++) {
            int cidx = n0 + tx * 8 + j;
            float v = acc[i][j];
            if (EPI == 1) v = fmaxf(v * scale[cidx] + shift[cidx], 0.f);
            Cm[(size_t)row * Nn + cidx] = v;
        }
    }
}

// ---------------- CSR build ----------------
__global__ void hist_kernel(const int* __restrict__ ei, const int* __restrict__ ew) {
    int e = blockIdx.x * blockDim.x + threadIdx.x;
    if (e < EE && ew[e] == 1) atomicAdd(&g_deg[ei[EE + e]], 1);
}

__global__ void scan_blocks() {
    __shared__ int s[512];
    int tid = threadIdx.x;
    int i = blockIdx.x * 512 + tid;
    int v = (i < NN) ? g_deg[i] : 0;
    s[tid] = v;
    __syncthreads();
    for (int off = 1; off < 512; off <<= 1) {
        int u = (tid >= off) ? s[tid - off] : 0;
        __syncthreads();
        s[tid] += u;
        __syncthreads();
    }
    if (i < NN) g_off[i] = s[tid] - v;
    if (tid == 511) g_bsum[blockIdx.x] = s[511];
}

__global__ void scan_sums() {
    __shared__ int s[64];
    int t = threadIdx.x;
    int nblk = (NN + 511) / 512;
    int v = (t < nblk) ? g_bsum[t] : 0;
    s[t] = v;
    __syncthreads();
    for (int off = 1; off < 64; off <<= 1) {
        int u = (t >= off) ? s[t - off] : 0;
        __syncthreads();
        s[t] += u;
        __syncthreads();
    }
    if (t < nblk) g_bsum[t] = s[t] - v;
    if (t == 63) g_off[NN] = s[63];
}

__global__ void scan_add() {
    int i = blockIdx.x * blockDim.x + threadIdx.x;
    if (i < NN) {
        int v = g_off[i] + g_bsum[i >> 9];
        g_off[i] = v;
        g_cur[i] = v;
    }
}

__global__ void scatter_kernel(const int* __restrict__ ei, const int* __restrict__ ew) {
    int e = blockIdx.x * blockDim.x + threadIdx.x;
    if (e < EE && ew[e] == 1) {
        int d = ei[EE + e];
        int pos = atomicAdd(&g_cur[d], 1);
        g_csr[pos] = ei[e];  // store src node id
    }
}

// ---------------- per-(node,head) attention logits ----------------
__global__ void logits_kernel(const float* __restrict__ xw,
                              const float* __restrict__ asrc,
                              const float* __restrict__ adst) {
    int gw = (blockIdx.x * blockDim.x + threadIdx.x) >> 5;
    int lane = threadIdx.x & 31;
    if (gw >= NN * HH) return;
    int n = gw >> 1, h = gw & 1;
    const float* row = xw + (size_t)n * D1 + h * CC;
    const float* as = asrc + h * CC;
    const float* ad = adst + h * CC;
    float s = 0.f, d = 0.f;
    for (int c = lane; c < CC; c += 32) {
        float v = row[c];
        s += v * as[c];
        d += v * ad[c];
    }
#pragma unroll
    for (int o = 16; o; o >>= 1) {
        s += __shfl_xor_sync(0xffffffffu, s, o);
        d += __shfl_xor_sync(0xffffffffu, d, o);
    }
    if (!lane) {
        g_ls[n * 2 + h] = s;
        g_ld[n * 2 + h] = d;
    }
}

// ---------------- GAT aggregation: one block per destination node ----------------
__global__ void __launch_bounds__(256) gat_agg(const float* __restrict__ xw,
                                               const float* __restrict__ bias,
                                               float* __restrict__ out) {
    int n = blockIdx.x;
    int t = threadIdx.x, lane = t & 31, wrp = t >> 5;
    int beg = g_off[n], end = g_off[n + 1];
    int deg = end - beg;
    __shared__ float sp0[256], sp1[256];
    __shared__ int ssrc[256];
    __shared__ float red[20];
    float ld0 = g_ld[n * 2], ld1 = g_ld[n * 2 + 1];

    // phase 1: segment max per head
    float m0 = -1e30f, m1 = -1e30f;
    for (int i = t; i < deg; i += 256) {
        int s = g_csr[beg + i];
        float e0 = g_ls[s * 2] + ld0;     e0 = e0 > 0.f ? e0 : 0.2f * e0;
        float e1 = g_ls[s * 2 + 1] + ld1; e1 = e1 > 0.f ? e1 : 0.2f * e1;
        m0 = fmaxf(m0, e0);
        m1 = fmaxf(m1, e1);
    }
#pragma unroll
    for (int o = 16; o; o >>= 1) {
        m0 = fmaxf(m0, __shfl_xor_sync(0xffffffffu, m0, o));
        m1 = fmaxf(m1, __shfl_xor_sync(0xffffffffu, m1, o));
    }
    if (!lane) { red[wrp] = m0; red[8 + wrp] = m1; }
    __syncthreads();
    if (t == 0) {
        float a = -1e30f, b = -1e30f;
        for (int w = 0; w < 8; w++) { a = fmaxf(a, red[w]); b = fmaxf(b, red[8 + w]); }
        red[16] = a; red[17] = b;
    }
    __syncthreads();
    float M0 = red[16], M1 = red[17];

    // phase 2: exp + message accumulation, chunked through smem
    float acc0 = 0.f, acc1 = 0.f, den0 = 0.f, den1 = 0.f;
    for (int base = 0; base < deg; base += 256) {
        int i = base + t;
        float p0 = 0.f, p1 = 0.f;
        int s = 0;
        if (i < deg) {
            s = g_csr[beg + i];
            float e0 = g_ls[s * 2] + ld0;     e0 = e0 > 0.f ? e0 : 0.2f * e0;
            float e1 = g_ls[s * 2 + 1] + ld1; e1 = e1 > 0.f ? e1 : 0.2f * e1;
            p0 = __expf(e0 - M0);
            p1 = __expf(e1 - M1);
        }
        __syncthreads();
        sp0[t] = p0; sp1[t] = p1; ssrc[t] = s;
        den0 += p0; den1 += p1;
        __syncthreads();
        int cnt = min(256, deg - base);
        for (int j = 0; j < cnt; j++) {
            const float* row = xw + (size_t)ssrc[j] * D1;
            acc0 += sp0[j] * row[t];
            acc1 += sp1[j] * row[256 + t];
        }
    }
    // reduce denominators
#pragma unroll
    for (int o = 16; o; o >>= 1) {
        den0 += __shfl_xor_sync(0xffffffffu, den0, o);
        den1 += __shfl_xor_sync(0xffffffffu, den1, o);
    }
    __syncthreads();
    if (!lane) { red[wrp] = den0; red[8 + wrp] = den1; }
    __syncthreads();
    if (t == 0) {
        float a = 0.f, b = 0.f;
        for (int w = 0; w < 8; w++) { a += red[w]; b += red[8 + w]; }
        red[16] = a; red[17] = b;
    }
    __syncthreads();
    float Dn0 = red[16] + 1e-16f, Dn1 = red[17] + 1e-16f;
    out[(size_t)n * D1 + t]       = acc0 / Dn0 + bias[t];
    out[(size_t)n * D1 + 256 + t] = acc1 / Dn1 + bias[256 + t];
}

// ---------------- graph pooling (mean) via atomics ----------------
__global__ void pool_kernel(const float* __restrict__ h, const int* __restrict__ batch) {
    int n = blockIdx.x;
    int t = threadIdx.x;
    int g = batch[n];
    atomicAdd(&g_pool[(size_t)g * D1 + t], h[(size_t)n * D1 + t]);
    atomicAdd(&g_pool[(size_t)g * D1 + 256 + t], h[(size_t)n * D1 + 256 + t]);
    if (t == 0) atomicAdd(&g_cnt[g], 1.0f);
}

// ---------------- final head: BN -> ReLU -> Linear -> ReLU -> Linear ----------------
__global__ void __launch_bounds__(512) final_head(
    const float* __restrict__ bn3g, const float* __restrict__ bn3b,
    const float* __restrict__ bn3m, const float* __restrict__ bn3v,
    const float* __restrict__ w1, const float* __restrict__ b1,
    const float* __restrict__ w2, const float* __restrict__ b2,
    float* __restrict__ out)
{
    int g = blockIdx.x, t = threadIdx.x;
    __shared__ float z[512];
    __shared__ float s1[512];
    float cnt = fmaxf(g_cnt[g], 1.0f);
    float pv = g_pool[(size_t)g * D1 + t] / cnt;
    float sc = bn3g[t] * rsqrtf(bn3v[t] + 1e-5f);
    z[t] = fmaxf((pv - bn3m[t]) * sc + bn3b[t], 0.f);
    __syncthreads();
    float a = 0.f;
    for (int k = 0; k < 512; k++) a += z[k] * w1[(size_t)k * 512 + t];
    s1[t] = fmaxf(a + b1[t], 0.f);
    __syncthreads();
    if (t < NC * 32) {
        int col = t >> 5, lane = t & 31;
        float s = 0.f;
        for (int k = lane; k < 512; k += 32) s += s1[k] * w2[k * NC + col];
#pragma unroll
        for (int o = 16; o; o >>= 1) s += __shfl_xor_sync(0xffffffffu, s, o);
        if (!lane) out[g * NC + col] = s + b2[col];
    }
}

// ---------------- host launcher ----------------
extern "C" void kernel_launch(void* const* d_in, const int* in_sizes, int n_in,
                              void* d_out, int out_size) {
    const float* x        = (const float*)d_in[0];
    const int*   ei       = (const int*)d_in[1];
    const int*   ew       = (const int*)d_in[2];
    const int*   batch    = (const int*)d_in[3];
    const float* mlp_w1   = (const float*)d_in[4];
    const float* mlp_b1   = (const float*)d_in[5];
    const float* bn1_g    = (const float*)d_in[6];
    const float* bn1_b    = (const float*)d_in[7];
    const float* bn1_m    = (const float*)d_in[8];
    const float* bn1_v    = (const float*)d_in[9];
    const float* mlp_w2   = (const float*)d_in[10];
    const float* mlp_b2   = (const float*)d_in[11];
    const float* bn2_g    = (const float*)d_in[12];
    const float* bn2_b    = (const float*)d_in[13];
    const float* bn2_m    = (const float*)d_in[14];
    const float* bn2_v    = (const float*)d_in[15];
    const float* gat0_w   = (const float*)d_in[16];
    const float* gat0_as  = (const float*)d_in[17];
    const float* gat0_ad  = (const float*)d_in[18];
    const float* gat0_bi  = (const float*)d_in[19];
    const float* gat1_w   = (const float*)d_in[20];
    const float* gat1_as  = (const float*)d_in[21];
    const float* gat1_ad  = (const float*)d_in[22];
    const float* gat1_bi  = (const float*)d_in[23];
    const float* bn3_g    = (const float*)d_in[24];
    const float* bn3_b    = (const float*)d_in[25];
    const float* bn3_m    = (const float*)d_in[26];
    const float* bn3_v    = (const float*)d_in[27];
    const float* fin_w1   = (const float*)d_in[28];
    const float* fin_b1   = (const float*)d_in[29];
    const float* fin_w2   = (const float*)d_in[30];
    const float* fin_b2   = (const float*)d_in[31];
    float* out = (float*)d_out;

    float *hp_h1, *hp_h2, *hp_xw, *hp_h3, *hp_h4, *hp_sc1, *hp_sh1, *hp_sc2, *hp_sh2;
    cudaGetSymbolAddress((void**)&hp_h1, g_h1);
    cudaGetSymbolAddress((void**)&hp_h2, g_h2);
    cudaGetSymbolAddress((void**)&hp_xw, g_xw);
    cudaGetSymbolAddress((void**)&hp_h3, g_h3);
    cudaGetSymbolAddress((void**)&hp_h4, g_h4);
    cudaGetSymbolAddress((void**)&hp_sc1, g_sc1);
    cudaGetSymbolAddress((void**)&hp_sh1, g_sh1);
    cudaGetSymbolAddress((void**)&hp_sc2, g_sc2);
    cudaGetSymbolAddress((void**)&hp_sh2, g_sh2);

    // 1) zero per-call state + BN prep
    zero_kernel<<<(GG * D1 + 255) / 256, 256>>>();
    prep_bn<<<1, 256>>>(mlp_b1, bn1_g, bn1_b, bn1_m, bn1_v,
                        mlp_b2, bn2_g, bn2_b, bn2_m, bn2_v);

    // 2) node MLP
    dim3 g1(D0 / 128, (NN + 127) / 128);
    sgemm<1><<<g1, 256>>>(x, mlp_w1, hp_h1, NN, D0, FF, hp_sc1, hp_sh1);
    sgemm<1><<<g1, 256>>>(hp_h1, mlp_w2, hp_h2, NN, D0, D0, hp_sc2, hp_sh2);

    // 3) CSR by dst
    hist_kernel<<<(EE + 255) / 256, 256>>>(ei, ew);
    scan_blocks<<<(NN + 511) / 512, 512>>>();
    scan_sums<<<1, 64>>>();
    scan_add<<<(NN + 255) / 256, 256>>>();
    scatter_kernel<<<(EE + 255) / 256, 256>>>(ei, ew);

    // 4) GAT layer 0
    dim3 g2(D1 / 128, (NN + 127) / 128);
    sgemm<0><<<g2, 256>>>(hp_h2, gat0_w, hp_xw, NN, D1, D0, nullptr, nullptr);
    logits_kernel<<<(NN * HH * 32 + 255) / 256, 256>>>(hp_xw, gat0_as, gat0_ad);
    gat_agg<<<NN, 256>>>(hp_xw, gat0_bi, hp_h3);

    // 5) GAT layer 1
    sgemm<0><<<g2, 256>>>(hp_h3, gat1_w, hp_xw, NN, D1, D1, nullptr, nullptr);
    logits_kernel<<<(NN * HH * 32 + 255) / 256, 256>>>(hp_xw, gat1_as, gat1_ad);
    gat_agg<<<NN, 256>>>(hp_xw, gat1_bi, hp_h4);

    // 6) pool + final head
    pool_kernel<<<NN, 256>>>(hp_h4, batch);
    final_head<<<GG, 512>>>(bn3_g, bn3_b, bn3_m, bn3_v,
                            fin_w1, fin_b1, fin_w2, fin_b2, out);
}

// round 3
// speedup vs baseline: 1.8183x; 1.8183x over previous
#include <cuda_runtime.h>
#include <cstdint>

#define NN 20000
#define EE 320000
#define FF 128
#define D0 256
#define D1 512
#define HH 2
#define CC 256
#define GG 128
#define NC 10

// ---------------- scratch (device globals; no allocation allowed) ----------------
__device__ float g_rx[NN * FF];        // tf32-rounded x
__device__ float g_h1[NN * D0];
__device__ float g_h2[NN * D0];
__device__ float g_xw[NN * D1];
__device__ float g_h3[NN * D1];
__device__ float g_h4[NN * D1];
__device__ float g_wt[D1 * D1];        // transposed weight staging (max 512x512)
__device__ float g_ls[NN * HH];
__device__ float g_ld[NN * HH];
__device__ int   g_deg[NN];
__device__ int   g_off[NN + 1];
__device__ int   g_cur[NN];
__device__ int   g_csr[EE];
__device__ int   g_bsum[64];
__device__ float g_sc1[D0], g_sh1[D0], g_sc2[D0], g_sh2[D0];
__device__ float g_pool[GG * D1];
__device__ float g_cnt[GG];

// ---------------- small helpers ----------------
__device__ __forceinline__ float rtf32(float x) {
    uint32_t u;
    asm("cvt.rna.tf32.f32 %0, %1;" : "=r"(u) : "f"(x));
    return __uint_as_float(u);
}
__device__ __forceinline__ uint32_t smem_u32(const void* p) {
    uint32_t a;
    asm("{ .reg .u64 t; cvta.to.shared.u64 t, %1; cvt.u32.u64 %0, t; }" : "=r"(a) : "l"(p));
    return a;
}
__device__ __forceinline__ void cpa16(uint32_t dst, const void* src, int sz) {
    asm volatile("cp.async.ca.shared.global [%0], [%1], 16, %2;"
                 :: "r"(dst), "l"(src), "r"(sz));
}
__device__ __forceinline__ void cp_commit() {
    asm volatile("cp.async.commit_group;");
}
template <int N>
__device__ __forceinline__ void cp_wait() {
    asm volatile("cp.async.wait_group %0;" :: "n"(N));
}
__device__ __forceinline__ void mma_tf32(float* d, const float* a, const float* b) {
    asm volatile(
        "mma.sync.aligned.m16n8k8.row.col.f32.tf32.tf32.f32 "
        "{%0,%1,%2,%3}, {%4,%5,%6,%7}, {%8,%9}, {%0,%1,%2,%3};"
        : "+f"(d[0]), "+f"(d[1]), "+f"(d[2]), "+f"(d[3])
        : "r"(__float_as_uint(a[0])), "r"(__float_as_uint(a[1])),
          "r"(__float_as_uint(a[2])), "r"(__float_as_uint(a[3])),
          "r"(__float_as_uint(b[0])), "r"(__float_as_uint(b[1])));
}

// ---------------- zero per-call state ----------------
__global__ void zero_kernel() {
    int i = blockIdx.x * blockDim.x + threadIdx.x;
    if (i < GG * D1) g_pool[i] = 0.f;
    if (i < NN) g_deg[i] = 0;
    if (i < GG) g_cnt[i] = 0.f;
}

// ---------------- round x to tf32 ----------------
__global__ void round_x(const float* __restrict__ x) {
    int i = blockIdx.x * blockDim.x + threadIdx.x;
    if (i < NN * FF) g_rx[i] = rtf32(x[i]);
}

// ---------------- fold BN (eval) + linear bias into scale/shift ----------------
__global__ void prep_bn(const float* lb1, const float* g1, const float* b1,
                        const float* m1, const float* v1,
                        const float* lb2, const float* g2, const float* b2,
                        const float* m2, const float* v2) {
    int t = threadIdx.x;
    if (t < D0) {
        float sc = g1[t] * rsqrtf(v1[t] + 1e-5f);
        g_sc1[t] = sc;
        g_sh1[t] = (lb1[t] - m1[t]) * sc + b1[t];
        float sc2 = g2[t] * rsqrtf(v2[t] + 1e-5f);
        g_sc2[t] = sc2;
        g_sh2[t] = (lb2[t] - m2[t]) * sc2 + b2[t];
    }
}

// ---------------- weight transpose + tf32 round: W[K][N] -> Wt[N][K] ----------------
__global__ void transpose_k(const float* __restrict__ W, float* __restrict__ Wt,
                            int K, int N) {
    __shared__ float t[32][33];
    int bx = blockIdx.x * 32, by = blockIdx.y * 32;
    int x = threadIdx.x, y = threadIdx.y;
#pragma unroll
    for (int i = 0; i < 32; i += 8)
        t[y + i][x] = W[(size_t)(by + y + i) * N + bx + x];
    __syncthreads();
#pragma unroll
    for (int i = 0; i < 32; i += 8)
        Wt[(size_t)(bx + y + i) * K + by + x] = rtf32(t[x][y + i]);
}

// ---------------- tf32 mma.sync GEMM: C[M,N] = A[M,K] @ Bt[N,K]^T ----------------
// EPI==0: plain fp32 store. EPI==1: rtf32(relu(acc*scale[n]+shift[n]))
// BM=128, BN=128, BK=16, 8 warps (4m x 2n), warp tile 32x64, 2-stage cp.async.
template <int EPI>
__global__ void __launch_bounds__(256, 2) tgemm(
    const float* __restrict__ A, const float* __restrict__ Bt,
    float* __restrict__ Cm, int M, int Nn, int K,
    const float* __restrict__ scale, const float* __restrict__ shift)
{
    const int LDS_ = 20;  // 16 + 4 pad floats
    __shared__ float As[2][128 * LDS_];
    __shared__ float Bs[2][128 * LDS_];

    const int tid = threadIdx.x;
    const int wid = tid >> 5, lane = tid & 31;
    const int wm = wid & 3, wn = wid >> 2;
    const int lr = lane >> 2, lc = lane & 3;
    const int m0 = blockIdx.y * 128, n0 = blockIdx.x * 128;

    // cp.async indices: 512 float4 per tile, 256 threads -> 2 each
    const int arow0 = tid >> 1;                 // +64 for second
    const int ac4 = (tid & 1) * 2;              // float4 col pairs: handles 2 consecutive? no:
    // layout: each thread does 2 chunks: (row = tid>>1, c4 = (tid&1)*2 + {0,1})
    uint32_t sA[2], sB[2];
    sA[0] = smem_u32(&As[0][0]);
    sA[1] = smem_u32(&As[1][0]);
    sB[0] = smem_u32(&Bs[0][0]);
    sB[1] = smem_u32(&Bs[1][0]);

    float acc[2][8][4];
#pragma unroll
    for (int i = 0; i < 2; i++)
#pragma unroll
        for (int j = 0; j < 8; j++)
#pragma unroll
            for (int q = 0; q < 4; q++) acc[i][j][q] = 0.f;

    const int nch = K >> 4;

    // ---- load chunk ch into stage st ----
    auto load_chunk = [&](int ch, int st) {
        int k0 = ch << 4;
#pragma unroll
        for (int i = 0; i < 2; i++) {
            int row = arow0;
            int c4 = ac4 + i;
            // A
            int gr = m0 + row;
            int ok = (gr < M) ? 16 : 0;
            int grc = (gr < M) ? gr : (M - 1);
            cpa16(sA[st] + (uint32_t)(row * LDS_ + c4 * 4) * 4u,
                  A + (size_t)grc * K + k0 + c4 * 4, ok);
            // B (always valid: Nn multiple of 128)
            cpa16(sB[st] + (uint32_t)(row * LDS_ + c4 * 4) * 4u,
                  Bt + (size_t)(n0 + row) * K + k0 + c4 * 4, 16);
        }
        cp_commit();
    };

    load_chunk(0, 0);

    for (int ch = 0; ch < nch; ch++) {
        int st = ch & 1;
        if (ch + 1 < nch) {
            load_chunk(ch + 1, st ^ 1);
            cp_wait<1>();
        } else {
            cp_wait<0>();
        }
        __syncthreads();

        const float* Ab = &As[st][(wm * 32 + lr) * LDS_ + lc];
        const float* Bb = &Bs[st][(wn * 64 + lr) * LDS_ + lc];
#pragma unroll
        for (int ks = 0; ks < 2; ks++) {
            int k0 = ks * 8;
            float a[2][4], b[8][2];
#pragma unroll
            for (int mt = 0; mt < 2; mt++) {
                a[mt][0] = Ab[(mt * 16) * LDS_ + k0];
                a[mt][1] = Ab[(mt * 16 + 8) * LDS_ + k0];
                a[mt][2] = Ab[(mt * 16) * LDS_ + k0 + 4];
                a[mt][3] = Ab[(mt * 16 + 8) * LDS_ + k0 + 4];
            }
#pragma unroll
            for (int nt = 0; nt < 8; nt++) {
                b[nt][0] = Bb[(nt * 8) * LDS_ + k0];
                b[nt][1] = Bb[(nt * 8) * LDS_ + k0 + 4];
            }
#pragma unroll
            for (int mt = 0; mt < 2; mt++)
#pragma unroll
                for (int nt = 0; nt < 8; nt++)
                    mma_tf32(acc[mt][nt], a[mt], b[nt]);
        }
        __syncthreads();
    }

    // ---- epilogue ----
#pragma unroll
    for (int mt = 0; mt < 2; mt++) {
        int row0 = m0 + wm * 32 + mt * 16 + lr;
#pragma unroll
        for (int nt = 0; nt < 8; nt++) {
            int col = n0 + wn * 64 + nt * 8 + lc * 2;
            float v0 = acc[mt][nt][0], v1 = acc[mt][nt][1];
            float v2 = acc[mt][nt][2], v3 = acc[mt][nt][3];
            if (EPI == 1) {
                float s0 = scale[col], s1 = scale[col + 1];
                float h0 = shift[col], h1 = shift[col + 1];
                v0 = rtf32(fmaxf(v0 * s0 + h0, 0.f));
                v1 = rtf32(fmaxf(v1 * s1 + h1, 0.f));
                v2 = rtf32(fmaxf(v2 * s0 + h0, 0.f));
                v3 = rtf32(fmaxf(v3 * s1 + h1, 0.f));
            }
            if (row0 < M)
                *(float2*)(Cm + (size_t)row0 * Nn + col) = make_float2(v0, v1);
            if (row0 + 8 < M)
                *(float2*)(Cm + (size_t)(row0 + 8) * Nn + col) = make_float2(v2, v3);
        }
    }
}

// ---------------- CSR build ----------------
__global__ void hist_kernel(const int* __restrict__ ei, const int* __restrict__ ew) {
    int e = blockIdx.x * blockDim.x + threadIdx.x;
    if (e < EE && ew[e] == 1) atomicAdd(&g_deg[ei[EE + e]], 1);
}

__global__ void scan_blocks() {
    __shared__ int s[512];
    int tid = threadIdx.x;
    int i = blockIdx.x * 512 + tid;
    int v = (i < NN) ? g_deg[i] : 0;
    s[tid] = v;
    __syncthreads();
    for (int off = 1; off < 512; off <<= 1) {
        int u = (tid >= off) ? s[tid - off] : 0;
        __syncthreads();
        s[tid] += u;
        __syncthreads();
    }
    if (i < NN) g_off[i] = s[tid] - v;
    if (tid == 511) g_bsum[blockIdx.x] = s[511];
}

__global__ void scan_sums() {
    __shared__ int s[64];
    int t = threadIdx.x;
    int nblk = (NN + 511) / 512;
    int v = (t < nblk) ? g_bsum[t] : 0;
    s[t] = v;
    __syncthreads();
    for (int off = 1; off < 64; off <<= 1) {
        int u = (t >= off) ? s[t - off] : 0;
        __syncthreads();
        s[t] += u;
        __syncthreads();
    }
    if (t < nblk) g_bsum[t] = s[t] - v;
    if (t == 63) g_off[NN] = s[63];
}

__global__ void scan_add() {
    int i = blockIdx.x * blockDim.x + threadIdx.x;
    if (i < NN) {
        int v = g_off[i] + g_bsum[i >> 9];
        g_off[i] = v;
        g_cur[i] = v;
    }
}

__global__ void scatter_kernel(const int* __restrict__ ei, const int* __restrict__ ew) {
    int e = blockIdx.x * blockDim.x + threadIdx.x;
    if (e < EE && ew[e] == 1) {
        int d = ei[EE + e];
        int pos = atomicAdd(&g_cur[d], 1);
        g_csr[pos] = ei[e];
    }
}

// ---------------- per-(node,head) attention logits ----------------
__global__ void logits_kernel(const float* __restrict__ xw,
                              const float* __restrict__ asrc,
                              const float* __restrict__ adst) {
    int gw = (blockIdx.x * blockDim.x + threadIdx.x) >> 5;
    int lane = threadIdx.x & 31;
    if (gw >= NN * HH) return;
    int n = gw >> 1, h = gw & 1;
    const float* row = xw + (size_t)n * D1 + h * CC;
    const float* as = asrc + h * CC;
    const float* ad = adst + h * CC;
    float s = 0.f, d = 0.f;
    for (int c = lane; c < CC; c += 32) {
        float v = row[c];
        s += v * as[c];
        d += v * ad[c];
    }
#pragma unroll
    for (int o = 16; o; o >>= 1) {
        s += __shfl_xor_sync(0xffffffffu, s, o);
        d += __shfl_xor_sync(0xffffffffu, d, o);
    }
    if (!lane) {
        g_ls[n * 2 + h] = s;
        g_ld[n * 2 + h] = d;
    }
}

// ---------------- GAT aggregation: one block per destination node ----------------
// ROUND==1: round output to tf32 (feeds next GEMM)
template <int ROUND>
__global__ void __launch_bounds__(256) gat_agg(const float* __restrict__ xw,
                                               const float* __restrict__ bias,
                                               float* __restrict__ out) {
    int n = blockIdx.x;
    int t = threadIdx.x, lane = t & 31, wrp = t >> 5;
    int beg = g_off[n], end = g_off[n + 1];
    int deg = end - beg;
    __shared__ float sp0[256], sp1[256];
    __shared__ int ssrc[256];
    __shared__ float red[20];
    float ld0 = g_ld[n * 2], ld1 = g_ld[n * 2 + 1];

    float m0 = -1e30f, m1 = -1e30f;
    for (int i = t; i < deg; i += 256) {
        int s = g_csr[beg + i];
        float e0 = g_ls[s * 2] + ld0;     e0 = e0 > 0.f ? e0 : 0.2f * e0;
        float e1 = g_ls[s * 2 + 1] + ld1; e1 = e1 > 0.f ? e1 : 0.2f * e1;
        m0 = fmaxf(m0, e0);
        m1 = fmaxf(m1, e1);
    }
#pragma unroll
    for (int o = 16; o; o >>= 1) {
        m0 = fmaxf(m0, __shfl_xor_sync(0xffffffffu, m0, o));
        m1 = fmaxf(m1, __shfl_xor_sync(0xffffffffu, m1, o));
    }
    if (!lane) { red[wrp] = m0; red[8 + wrp] = m1; }
    __syncthreads();
    if (t == 0) {
        float a = -1e30f, b = -1e30f;
        for (int w = 0; w < 8; w++) { a = fmaxf(a, red[w]); b = fmaxf(b, red[8 + w]); }
        red[16] = a; red[17] = b;
    }
    __syncthreads();
    float M0 = red[16], M1 = red[17];

    float acc0 = 0.f, acc1 = 0.f, den0 = 0.f, den1 = 0.f;
    for (int base = 0; base < deg; base += 256) {
        int i = base + t;
        float p0 = 0.f, p1 = 0.f;
        int s = 0;
        if (i < deg) {
            s = g_csr[beg + i];
            float e0 = g_ls[s * 2] + ld0;     e0 = e0 > 0.f ? e0 : 0.2f * e0;
            float e1 = g_ls[s * 2 + 1] + ld1; e1 = e1 > 0.f ? e1 : 0.2f * e1;
            p0 = __expf(e0 - M0);
            p1 = __expf(e1 - M1);
        }
        __syncthreads();
        sp0[t] = p0; sp1[t] = p1; ssrc[t] = s;
        den0 += p0; den1 += p1;
        __syncthreads();
        int cnt = min(256, deg - base);
        for (int j = 0; j < cnt; j++) {
            const float* row = xw + (size_t)ssrc[j] * D1;
            acc0 += sp0[j] * row[t];
            acc1 += sp1[j] * row[256 + t];
        }
    }
#pragma unroll
    for (int o = 16; o; o >>= 1) {
        den0 += __shfl_xor_sync(0xffffffffu, den0, o);
        den1 += __shfl_xor_sync(0xffffffffu, den1, o);
    }
    __syncthreads();
    if (!lane) { red[wrp] = den0; red[8 + wrp] = den1; }
    __syncthreads();
    if (t == 0) {
        float a = 0.f, b = 0.f;
        for (int w = 0; w < 8; w++) { a += red[w]; b += red[8 + w]; }
        red[16] = a; red[17] = b;
    }
    __syncthreads();
    float Dn0 = red[16] + 1e-16f, Dn1 = red[17] + 1e-16f;
    float o0 = acc0 / Dn0 + bias[t];
    float o1 = acc1 / Dn1 + bias[256 + t];
    if (ROUND) { o0 = rtf32(o0); o1 = rtf32(o1); }
    out[(size_t)n * D1 + t]       = o0;
    out[(size_t)n * D1 + 256 + t] = o1;
}

// ---------------- graph pooling (mean) via atomics ----------------
__global__ void pool_kernel(const float* __restrict__ h, const int* __restrict__ batch) {
    int n = blockIdx.x;
    int t = threadIdx.x;
    int g = batch[n];
    atomicAdd(&g_pool[(size_t)g * D1 + t], h[(size_t)n * D1 + t]);
    atomicAdd(&g_pool[(size_t)g * D1 + 256 + t], h[(size_t)n * D1 + 256 + t]);
    if (t == 0) atomicAdd(&g_cnt[g], 1.0f);
}

// ---------------- final head ----------------
__global__ void __launch_bounds__(512) final_head(
    const float* __restrict__ bn3g, const float* __restrict__ bn3b,
    const float* __restrict__ bn3m, const float* __restrict__ bn3v,
    const float* __restrict__ w1, const float* __restrict__ b1,
    const float* __restrict__ w2, const float* __restrict__ b2,
    float* __restrict__ out)
{
    int g = blockIdx.x, t = threadIdx.x;
    __shared__ float z[512];
    __shared__ float s1[512];
    float cnt = fmaxf(g_cnt[g], 1.0f);
    float pv = g_pool[(size_t)g * D1 + t] / cnt;
    float sc = bn3g[t] * rsqrtf(bn3v[t] + 1e-5f);
    z[t] = fmaxf((pv - bn3m[t]) * sc + bn3b[t], 0.f);
    __syncthreads();
    float a = 0.f;
    for (int k = 0; k < 512; k++) a += z[k] * w1[(size_t)k * 512 + t];
    s1[t] = fmaxf(a + b1[t], 0.f);
    __syncthreads();
    if (t < NC * 32) {
        int col = t >> 5, lane = t & 31;
        float s = 0.f;
        for (int k = lane; k < 512; k += 32) s += s1[k] * w2[k * NC + col];
#pragma unroll
        for (int o = 16; o; o >>= 1) s += __shfl_xor_sync(0xffffffffu, s, o);
        if (!lane) out[g * NC + col] = s + b2[col];
    }
}

// ---------------- host launcher ----------------
extern "C" void kernel_launch(void* const* d_in, const int* in_sizes, int n_in,
                              void* d_out, int out_size) {
    const float* x        = (const float*)d_in[0];
    const int*   ei       = (const int*)d_in[1];
    const int*   ew       = (const int*)d_in[2];
    const int*   batch    = (const int*)d_in[3];
    const float* mlp_w1   = (const float*)d_in[4];
    const float* mlp_b1   = (const float*)d_in[5];
    const float* bn1_g    = (const float*)d_in[6];
    const float* bn1_b    = (const float*)d_in[7];
    const float* bn1_m    = (const float*)d_in[8];
    const float* bn1_v    = (const float*)d_in[9];
    const float* mlp_w2   = (const float*)d_in[10];
    const float* mlp_b2   = (const float*)d_in[11];
    const float* bn2_g    = (const float*)d_in[12];
    const float* bn2_b    = (const float*)d_in[13];
    const float* bn2_m    = (const float*)d_in[14];
    const float* bn2_v    = (const float*)d_in[15];
    const float* gat0_w   = (const float*)d_in[16];
    const float* gat0_as  = (const float*)d_in[17];
    const float* gat0_ad  = (const float*)d_in[18];
    const float* gat0_bi  = (const float*)d_in[19];
    const float* gat1_w   = (const float*)d_in[20];
    const float* gat1_as  = (const float*)d_in[21];
    const float* gat1_ad  = (const float*)d_in[22];
    const float* gat1_bi  = (const float*)d_in[23];
    const float* bn3_g    = (const float*)d_in[24];
    const float* bn3_b    = (const float*)d_in[25];
    const float* bn3_m    = (const float*)d_in[26];
    const float* bn3_v    = (const float*)d_in[27];
    const float* fin_w1   = (const float*)d_in[28];
    const float* fin_b1   = (const float*)d_in[29];
    const float* fin_w2   = (const float*)d_in[30];
    const float* fin_b2   = (const float*)d_in[31];
    float* out = (float*)d_out;

    float *hp_rx, *hp_h1, *hp_h2, *hp_xw, *hp_h3, *hp_h4, *hp_wt;
    float *hp_sc1, *hp_sh1, *hp_sc2, *hp_sh2;
    cudaGetSymbolAddress((void**)&hp_rx, g_rx);
    cudaGetSymbolAddress((void**)&hp_h1, g_h1);
    cudaGetSymbolAddress((void**)&hp_h2, g_h2);
    cudaGetSymbolAddress((void**)&hp_xw, g_xw);
    cudaGetSymbolAddress((void**)&hp_h3, g_h3);
    cudaGetSymbolAddress((void**)&hp_h4, g_h4);
    cudaGetSymbolAddress((void**)&hp_wt, g_wt);
    cudaGetSymbolAddress((void**)&hp_sc1, g_sc1);
    cudaGetSymbolAddress((void**)&hp_sh1, g_sh1);
    cudaGetSymbolAddress((void**)&hp_sc2, g_sc2);
    cudaGetSymbolAddress((void**)&hp_sh2, g_sh2);

    // 1) per-call state + BN prep + CSR build + x rounding
    zero_kernel<<<(GG * D1 + 255) / 256, 256>>>();
    prep_bn<<<1, 256>>>(mlp_b1, bn1_g, bn1_b, bn1_m, bn1_v,
                        mlp_b2, bn2_g, bn2_b, bn2_m, bn2_v);
    round_x<<<(NN * FF + 255) / 256, 256>>>(x);
    hist_kernel<<<(EE + 255) / 256, 256>>>(ei, ew);
    scan_blocks<<<(NN + 511) / 512, 512>>>();
    scan_sums<<<1, 64>>>();
    scan_add<<<(NN + 255) / 256, 256>>>();
    scatter_kernel<<<(EE + 255) / 256, 256>>>(ei, ew);

    const int MB = (NN + 127) / 128;  // 157

    // 2) node MLP (tf32 mma.sync)
    transpose_k<<<dim3(D0 / 32, FF / 32), dim3(32, 8)>>>(mlp_w1, hp_wt, FF, D0);
    tgemm<1><<<dim3(D0 / 128, MB), 256>>>(hp_rx, hp_wt, hp_h1, NN, D0, FF, hp_sc1, hp_sh1);
    transpose_k<<<dim3(D0 / 32, D0 / 32), dim3(32, 8)>>>(mlp_w2, hp_wt, D0, D0);
    tgemm<1><<<dim3(D0 / 128, MB), 256>>>(hp_h1, hp_wt, hp_h2, NN, D0, D0, hp_sc2, hp_sh2);

    // 3) GAT layer 0
    transpose_k<<<dim3(D1 / 32, D0 / 32), dim3(32, 8)>>>(gat0_w, hp_wt, D0, D1);
    tgemm<0><<<dim3(D1 / 128, MB), 256>>>(hp_h2, hp_wt, hp_xw, NN, D1, D0, nullptr, nullptr);
    logits_kernel<<<(NN * HH * 32 + 255) / 256, 256>>>(hp_xw, gat0_as, gat0_ad);
    gat_agg<1><<<NN, 256>>>(hp_xw, gat0_bi, hp_h3);

    // 4) GAT layer 1
    transpose_k<<<dim3(D1 / 32, D1 / 32), dim3(32, 8)>>>(gat1_w, hp_wt, D1, D1);
    tgemm<0><<<dim3(D1 / 128, MB), 256>>>(hp_h3, hp_wt, hp_xw, NN, D1, D1, nullptr, nullptr);
    logits_kernel<<<(NN * HH * 32 + 255) / 256, 256>>>(hp_xw, gat1_as, gat1_ad);
    gat_agg<0><<<NN, 256>>>(hp_xw, gat1_bi, hp_h4);

    // 5) pool + final head
    pool_kernel<<<NN, 256>>>(hp_h4, batch);
    final_head<<<GG, 512>>>(bn3_g, bn3_b, bn3_m, bn3_v,
                            fin_w1, fin_b1, fin_w2, fin_b2, out);
}

// round 4
// speedup vs baseline: 1.9379x; 1.0658x over previous
#include <cuda_runtime.h>
#include <cstdint>

#define NN 20000
#define EE 320000
#define FF 128
#define D0 256
#define D1 512
#define HH 2
#define CC 256
#define GG 128
#define NC 10

// ---------------- scratch (device globals; no allocation allowed) ----------------
__device__ float g_rx[NN * FF];        // tf32-rounded x
__device__ float g_h1[NN * D0];
__device__ float g_h2[NN * D0];
__device__ float g_xw[NN * D1];
__device__ float g_h3[NN * D1];
__device__ float g_h4[NN * D1];
__device__ float g_wt[D1 * D1];        // transposed weight staging (max 512x512)
__device__ float g_ls[NN * HH];
__device__ float g_ld[NN * HH];
__device__ int   g_deg[NN];
__device__ int   g_off[NN + 1];
__device__ int   g_cur[NN];
__device__ int   g_csr[EE];
__device__ int   g_bsum[64];
__device__ int   g_goff[GG + 1];
__device__ float g_sc1[D0], g_sh1[D0], g_sc2[D0], g_sh2[D0];
__device__ float g_pool[GG * D1];
__device__ float g_cnt[GG];

// ---------------- small helpers ----------------
__device__ __forceinline__ float rtf32(float x) {
    uint32_t u;
    asm("cvt.rna.tf32.f32 %0, %1;" : "=r"(u) : "f"(x));
    return __uint_as_float(u);
}
__device__ __forceinline__ uint32_t smem_u32(const void* p) {
    uint32_t a;
    asm("{ .reg .u64 t; cvta.to.shared.u64 t, %1; cvt.u32.u64 %0, t; }" : "=r"(a) : "l"(p));
    return a;
}
__device__ __forceinline__ void cpa16(uint32_t dst, const void* src, int sz) {
    asm volatile("cp.async.ca.shared.global [%0], [%1], 16, %2;"
                 :: "r"(dst), "l"(src), "r"(sz));
}
__device__ __forceinline__ void cp_commit() {
    asm volatile("cp.async.commit_group;");
}
template <int N>
__device__ __forceinline__ void cp_wait() {
    asm volatile("cp.async.wait_group %0;" :: "n"(N));
}
__device__ __forceinline__ void mma_tf32(float* d, const float* a, const float* b) {
    asm volatile(
        "mma.sync.aligned.m16n8k8.row.col.f32.tf32.tf32.f32 "
        "{%0,%1,%2,%3}, {%4,%5,%6,%7}, {%8,%9}, {%0,%1,%2,%3};"
        : "+f"(d[0]), "+f"(d[1]), "+f"(d[2]), "+f"(d[3])
        : "r"(__float_as_uint(a[0])), "r"(__float_as_uint(a[1])),
          "r"(__float_as_uint(a[2])), "r"(__float_as_uint(a[3])),
          "r"(__float_as_uint(b[0])), "r"(__float_as_uint(b[1])));
}

// ---------------- zero per-call state ----------------
__global__ void zero_kernel() {
    int i = blockIdx.x * blockDim.x + threadIdx.x;
    if (i < NN) g_deg[i] = 0;
}

// ---------------- round x to tf32 ----------------
__global__ void round_x(const float* __restrict__ x) {
    int i = blockIdx.x * blockDim.x + threadIdx.x;
    if (i < NN * FF) g_rx[i] = rtf32(x[i]);
}

// ---------------- fold BN (eval) + linear bias into scale/shift ----------------
__global__ void prep_bn(const float* lb1, const float* g1, const float* b1,
                        const float* m1, const float* v1,
                        const float* lb2, const float* g2, const float* b2,
                        const float* m2, const float* v2) {
    int t = threadIdx.x;
    if (t < D0) {
        float sc = g1[t] * rsqrtf(v1[t] + 1e-5f);
        g_sc1[t] = sc;
        g_sh1[t] = (lb1[t] - m1[t]) * sc + b1[t];
        float sc2 = g2[t] * rsqrtf(v2[t] + 1e-5f);
        g_sc2[t] = sc2;
        g_sh2[t] = (lb2[t] - m2[t]) * sc2 + b2[t];
    }
}

// ---------------- weight transpose + tf32 round: W[K][N] -> Wt[N][K] ----------------
__global__ void transpose_k(const float* __restrict__ W, float* __restrict__ Wt,
                            int K, int N) {
    __shared__ float t[32][33];
    int bx = blockIdx.x * 32, by = blockIdx.y * 32;
    int x = threadIdx.x, y = threadIdx.y;
#pragma unroll
    for (int i = 0; i < 32; i += 8)
        t[y + i][x] = W[(size_t)(by + y + i) * N + bx + x];
    __syncthreads();
#pragma unroll
    for (int i = 0; i < 32; i += 8)
        Wt[(size_t)(bx + y + i) * K + by + x] = rtf32(t[x][y + i]);
}

// ---------------- tf32 mma.sync GEMM: C[M,N] = A[M,K] @ Bt[N,K]^T ----------------
template <int EPI>
__global__ void __launch_bounds__(256, 2) tgemm(
    const float* __restrict__ A, const float* __restrict__ Bt,
    float* __restrict__ Cm, int M, int Nn, int K,
    const float* __restrict__ scale, const float* __restrict__ shift)
{
    const int LDS_ = 20;  // 16 + 4 pad floats
    __shared__ float As[2][128 * LDS_];
    __shared__ float Bs[2][128 * LDS_];

    const int tid = threadIdx.x;
    const int wid = tid >> 5, lane = tid & 31;
    const int wm = wid & 3, wn = wid >> 2;
    const int lr = lane >> 2, lc = lane & 3;
    const int m0 = blockIdx.y * 128, n0 = blockIdx.x * 128;

    const int arow0 = tid >> 1;
    const int ac4 = (tid & 1) * 2;
    uint32_t sA[2], sB[2];
    sA[0] = smem_u32(&As[0][0]);
    sA[1] = smem_u32(&As[1][0]);
    sB[0] = smem_u32(&Bs[0][0]);
    sB[1] = smem_u32(&Bs[1][0]);

    float acc[2][8][4];
#pragma unroll
    for (int i = 0; i < 2; i++)
#pragma unroll
        for (int j = 0; j < 8; j++)
#pragma unroll
            for (int q = 0; q < 4; q++) acc[i][j][q] = 0.f;

    const int nch = K >> 4;

    auto load_chunk = [&](int ch, int st) {
        int k0 = ch << 4;
#pragma unroll
        for (int i = 0; i < 2; i++) {
            int row = arow0;
            int c4 = ac4 + i;
            int gr = m0 + row;
            int ok = (gr < M) ? 16 : 0;
            int grc = (gr < M) ? gr : (M - 1);
            cpa16(sA[st] + (uint32_t)(row * LDS_ + c4 * 4) * 4u,
                  A + (size_t)grc * K + k0 + c4 * 4, ok);
            cpa16(sB[st] + (uint32_t)(row * LDS_ + c4 * 4) * 4u,
                  Bt + (size_t)(n0 + row) * K + k0 + c4 * 4, 16);
        }
        cp_commit();
    };

    load_chunk(0, 0);

    for (int ch = 0; ch < nch; ch++) {
        int st = ch & 1;
        if (ch + 1 < nch) {
            load_chunk(ch + 1, st ^ 1);
            cp_wait<1>();
        } else {
            cp_wait<0>();
        }
        __syncthreads();

        const float* Ab = &As[st][(wm * 32 + lr) * LDS_ + lc];
        const float* Bb = &Bs[st][(wn * 64 + lr) * LDS_ + lc];
#pragma unroll
        for (int ks = 0; ks < 2; ks++) {
            int k0 = ks * 8;
            float a[2][4], b[8][2];
#pragma unroll
            for (int mt = 0; mt < 2; mt++) {
                a[mt][0] = Ab[(mt * 16) * LDS_ + k0];
                a[mt][1] = Ab[(mt * 16 + 8) * LDS_ + k0];
                a[mt][2] = Ab[(mt * 16) * LDS_ + k0 + 4];
                a[mt][3] = Ab[(mt * 16 + 8) * LDS_ + k0 + 4];
            }
#pragma unroll
            for (int nt = 0; nt < 8; nt++) {
                b[nt][0] = Bb[(nt * 8) * LDS_ + k0];
                b[nt][1] = Bb[(nt * 8) * LDS_ + k0 + 4];
            }
#pragma unroll
            for (int mt = 0; mt < 2; mt++)
#pragma unroll
                for (int nt = 0; nt < 8; nt++)
                    mma_tf32(acc[mt][nt], a[mt], b[nt]);
        }
        __syncthreads();
    }

#pragma unroll
    for (int mt = 0; mt < 2; mt++) {
        int row0 = m0 + wm * 32 + mt * 16 + lr;
#pragma unroll
        for (int nt = 0; nt < 8; nt++) {
            int col = n0 + wn * 64 + nt * 8 + lc * 2;
            float v0 = acc[mt][nt][0], v1 = acc[mt][nt][1];
            float v2 = acc[mt][nt][2], v3 = acc[mt][nt][3];
            if (EPI == 1) {
                float s0 = scale[col], s1 = scale[col + 1];
                float h0 = shift[col], h1 = shift[col + 1];
                v0 = rtf32(fmaxf(v0 * s0 + h0, 0.f));
                v1 = rtf32(fmaxf(v1 * s1 + h1, 0.f));
                v2 = rtf32(fmaxf(v2 * s0 + h0, 0.f));
                v3 = rtf32(fmaxf(v3 * s1 + h1, 0.f));
            }
            if (row0 < M)
                *(float2*)(Cm + (size_t)row0 * Nn + col) = make_float2(v0, v1);
            if (row0 + 8 < M)
                *(float2*)(Cm + (size_t)(row0 + 8) * Nn + col) = make_float2(v2, v3);
        }
    }
}

// ---------------- CSR build ----------------
__global__ void hist_kernel(const int* __restrict__ ei, const int* __restrict__ ew) {
    int e = blockIdx.x * blockDim.x + threadIdx.x;
    if (e < EE && ew[e] == 1) atomicAdd(&g_deg[ei[EE + e]], 1);
}

__global__ void scan_blocks() {
    __shared__ int s[512];
    int tid = threadIdx.x;
    int i = blockIdx.x * 512 + tid;
    int v = (i < NN) ? g_deg[i] : 0;
    s[tid] = v;
    __syncthreads();
    for (int off = 1; off < 512; off <<= 1) {
        int u = (tid >= off) ? s[tid - off] : 0;
        __syncthreads();
        s[tid] += u;
        __syncthreads();
    }
    if (i < NN) g_off[i] = s[tid] - v;
    if (tid == 511) g_bsum[blockIdx.x] = s[511];
}

__global__ void scan_sums() {
    __shared__ int s[64];
    int t = threadIdx.x;
    int nblk = (NN + 511) / 512;
    int v = (t < nblk) ? g_bsum[t] : 0;
    s[t] = v;
    __syncthreads();
    for (int off = 1; off < 64; off <<= 1) {
        int u = (t >= off) ? s[t - off] : 0;
        __syncthreads();
        s[t] += u;
        __syncthreads();
    }
    if (t < nblk) g_bsum[t] = s[t] - v;
    if (t == 63) g_off[NN] = s[63];
}

__global__ void scan_add() {
    int i = blockIdx.x * blockDim.x + threadIdx.x;
    if (i < NN) {
        int v = g_off[i] + g_bsum[i >> 9];
        g_off[i] = v;
        g_cur[i] = v;
    }
}

__global__ void scatter_kernel(const int* __restrict__ ei, const int* __restrict__ ew) {
    int e = blockIdx.x * blockDim.x + threadIdx.x;
    if (e < EE && ew[e] == 1) {
        int d = ei[EE + e];
        int pos = atomicAdd(&g_cur[d], 1);
        g_csr[pos] = ei[e];
    }
}

// ---------------- per-(node,head) attention logits ----------------
__global__ void logits_kernel(const float* __restrict__ xw,
                              const float* __restrict__ asrc,
                              const float* __restrict__ adst) {
    int gw = (blockIdx.x * blockDim.x + threadIdx.x) >> 5;
    int lane = threadIdx.x & 31;
    if (gw >= NN * HH) return;
    int n = gw >> 1, h = gw & 1;
    const float* row = xw + (size_t)n * D1 + h * CC;
    const float* as = asrc + h * CC;
    const float* ad = adst + h * CC;
    float s = 0.f, d = 0.f;
    for (int c = lane; c < CC; c += 32) {
        float v = row[c];
        s += v * as[c];
        d += v * ad[c];
    }
#pragma unroll
    for (int o = 16; o; o >>= 1) {
        s += __shfl_xor_sync(0xffffffffu, s, o);
        d += __shfl_xor_sync(0xffffffffu, d, o);
    }
    if (!lane) {
        g_ls[n * 2 + h] = s;
        g_ld[n * 2 + h] = d;
    }
}

// ---------------- GAT aggregation: one WARP per destination node ----------------
// lane l owns channels {l*4..l*4+3} of each 128-float segment (4 segments = 512ch).
// segments 0,1 -> head0 ; segments 2,3 -> head1.
template <int ROUND>
__global__ void __launch_bounds__(256) gat_agg(const float* __restrict__ xw,
                                               const float* __restrict__ bias,
                                               float* __restrict__ out) {
    int gw = (blockIdx.x * blockDim.x + threadIdx.x) >> 5;
    if (gw >= NN) return;
    int lane = threadIdx.x & 31;
    int n = gw;
    int beg = g_off[n], end = g_off[n + 1];
    int deg = end - beg;
    float ld0 = g_ld[n * 2], ld1 = g_ld[n * 2 + 1];

    // pass 1: segment max per head
    float m0 = -1e30f, m1 = -1e30f;
    for (int i = lane; i < deg; i += 32) {
        int s = g_csr[beg + i];
        float e0 = g_ls[s * 2] + ld0;     e0 = e0 > 0.f ? e0 : 0.2f * e0;
        float e1 = g_ls[s * 2 + 1] + ld1; e1 = e1 > 0.f ? e1 : 0.2f * e1;
        m0 = fmaxf(m0, e0);
        m1 = fmaxf(m1, e1);
    }
#pragma unroll
    for (int o = 16; o; o >>= 1) {
        m0 = fmaxf(m0, __shfl_xor_sync(0xffffffffu, m0, o));
        m1 = fmaxf(m1, __shfl_xor_sync(0xffffffffu, m1, o));
    }

    // pass 2: weighted accumulation, 32 edges per chunk
    float4 a0 = make_float4(0.f, 0.f, 0.f, 0.f);
    float4 a1 = a0, a2 = a0, a3 = a0;
    float den0 = 0.f, den1 = 0.f;
    for (int base = 0; base < deg; base += 32) {
        int i = base + lane;
        float p0 = 0.f, p1 = 0.f;
        int sl = 0;
        if (i < deg) {
            sl = g_csr[beg + i];
            float e0 = g_ls[sl * 2] + ld0;     e0 = e0 > 0.f ? e0 : 0.2f * e0;
            float e1 = g_ls[sl * 2 + 1] + ld1; e1 = e1 > 0.f ? e1 : 0.2f * e1;
            p0 = __expf(e0 - m0);
            p1 = __expf(e1 - m1);
        }
        den0 += p0; den1 += p1;
        int cnt = min(32, deg - base);
        for (int j = 0; j < cnt; j++) {
            int s = __shfl_sync(0xffffffffu, sl, j);
            float q0 = __shfl_sync(0xffffffffu, p0, j);
            float q1 = __shfl_sync(0xffffffffu, p1, j);
            const float4* row = (const float4*)(xw + (size_t)s * D1);
            float4 v0 = row[lane];
            float4 v1 = row[32 + lane];
            float4 v2 = row[64 + lane];
            float4 v3 = row[96 + lane];
            a0.x += q0 * v0.x; a0.y += q0 * v0.y; a0.z += q0 * v0.z; a0.w += q0 * v0.w;
            a1.x += q0 * v1.x; a1.y += q0 * v1.y; a1.z += q0 * v1.z; a1.w += q0 * v1.w;
            a2.x += q1 * v2.x; a2.y += q1 * v2.y; a2.z += q1 * v2.z; a2.w += q1 * v2.w;
            a3.x += q1 * v3.x; a3.y += q1 * v3.y; a3.z += q1 * v3.z; a3.w += q1 * v3.w;
        }
    }
#pragma unroll
    for (int o = 16; o; o >>= 1) {
        den0 += __shfl_xor_sync(0xffffffffu, den0, o);
        den1 += __shfl_xor_sync(0xffffffffu, den1, o);
    }
    float r0 = 1.f / (den0 + 1e-16f), r1 = 1.f / (den1 + 1e-16f);

    const float4* bi = (const float4*)bias;
    float4* op = (float4*)(out + (size_t)n * D1);
    float4 b0 = bi[lane], b1 = bi[32 + lane], b2 = bi[64 + lane], b3 = bi[96 + lane];
    float4 o0 = make_float4(a0.x * r0 + b0.x, a0.y * r0 + b0.y, a0.z * r0 + b0.z, a0.w * r0 + b0.w);
    float4 o1 = make_float4(a1.x * r0 + b1.x, a1.y * r0 + b1.y, a1.z * r0 + b1.z, a1.w * r0 + b1.w);
    float4 o2 = make_float4(a2.x * r1 + b2.x, a2.y * r1 + b2.y, a2.z * r1 + b2.z, a2.w * r1 + b2.w);
    float4 o3 = make_float4(a3.x * r1 + b3.x, a3.y * r1 + b3.y, a3.z * r1 + b3.z, a3.w * r1 + b3.w);
    if (ROUND) {
        o0 = make_float4(rtf32(o0.x), rtf32(o0.y), rtf32(o0.z), rtf32(o0.w));
        o1 = make_float4(rtf32(o1.x), rtf32(o1.y), rtf32(o1.z), rtf32(o1.w));
        o2 = make_float4(rtf32(o2.x), rtf32(o2.y), rtf32(o2.z), rtf32(o2.w));
        o3 = make_float4(rtf32(o3.x), rtf32(o3.y), rtf32(o3.z), rtf32(o3.w));
    }
    op[lane] = o0;
    op[32 + lane] = o1;
    op[64 + lane] = o2;
    op[96 + lane] = o3;
}

// ---------------- graph segment starts (batch is sorted) ----------------
__global__ void graph_starts(const int* __restrict__ batch) {
    int g = blockIdx.x * blockDim.x + threadIdx.x;
    if (g > GG) return;
    int lo = 0, hi = NN;
    while (lo < hi) {
        int mid = (lo + hi) >> 1;
        if (batch[mid] < g) lo = mid + 1; else hi = mid;
    }
    g_goff[g] = lo;
}

// ---------------- graph pooling (sum; no atomics) ----------------
__global__ void __launch_bounds__(256) pool_kernel(const float* __restrict__ h) {
    int g = blockIdx.x, t = threadIdx.x;
    int s = g_goff[g], e = g_goff[g + 1];
    float a0 = 0.f, a1 = 0.f;
    for (int n = s; n < e; n++) {
        a0 += h[(size_t)n * D1 + t];
        a1 += h[(size_t)n * D1 + 256 + t];
    }
    g_pool[(size_t)g * D1 + t] = a0;
    g_pool[(size_t)g * D1 + 256 + t] = a1;
    if (t == 0) g_cnt[g] = (float)(e - s);
}

// ---------------- final head ----------------
__global__ void __launch_bounds__(512) final_head(
    const float* __restrict__ bn3g, const float* __restrict__ bn3b,
    const float* __restrict__ bn3m, const float* __restrict__ bn3v,
    const float* __restrict__ w1, const float* __restrict__ b1,
    const float* __restrict__ w2, const float* __restrict__ b2,
    float* __restrict__ out)
{
    int g = blockIdx.x, t = threadIdx.x;
    __shared__ float z[512];
    __shared__ float s1[512];
    float cnt = fmaxf(g_cnt[g], 1.0f);
    float pv = g_pool[(size_t)g * D1 + t] / cnt;
    float sc = bn3g[t] * rsqrtf(bn3v[t] + 1e-5f);
    z[t] = fmaxf((pv - bn3m[t]) * sc + bn3b[t], 0.f);
    __syncthreads();
    float a = 0.f;
    for (int k = 0; k < 512; k++) a += z[k] * w1[(size_t)k * 512 + t];
    s1[t] = fmaxf(a + b1[t], 0.f);
    __syncthreads();
    if (t < NC * 32) {
        int col = t >> 5, lane = t & 31;
        float s = 0.f;
        for (int k = lane; k < 512; k += 32) s += s1[k] * w2[k * NC + col];
#pragma unroll
        for (int o = 16; o; o >>= 1) s += __shfl_xor_sync(0xffffffffu, s, o);
        if (!lane) out[g * NC + col] = s + b2[col];
    }
}

// ---------------- host launcher ----------------
extern "C" void kernel_launch(void* const* d_in, const int* in_sizes, int n_in,
                              void* d_out, int out_size) {
    const float* x        = (const float*)d_in[0];
    const int*   ei       = (const int*)d_in[1];
    const int*   ew       = (const int*)d_in[2];
    const int*   batch    = (const int*)d_in[3];
    const float* mlp_w1   = (const float*)d_in[4];
    const float* mlp_b1   = (const float*)d_in[5];
    const float* bn1_g    = (const float*)d_in[6];
    const float* bn1_b    = (const float*)d_in[7];
    const float* bn1_m    = (const float*)d_in[8];
    const float* bn1_v    = (const float*)d_in[9];
    const float* mlp_w2   = (const float*)d_in[10];
    const float* mlp_b2   = (const float*)d_in[11];
    const float* bn2_g    = (const float*)d_in[12];
    const float* bn2_b    = (const float*)d_in[13];
    const float* bn2_m    = (const float*)d_in[14];
    const float* bn2_v    = (const float*)d_in[15];
    const float* gat0_w   = (const float*)d_in[16];
    const float* gat0_as  = (const float*)d_in[17];
    const float* gat0_ad  = (const float*)d_in[18];
    const float* gat0_bi  = (const float*)d_in[19];
    const float* gat1_w   = (const float*)d_in[20];
    const float* gat1_as  = (const float*)d_in[21];
    const float* gat1_ad  = (const float*)d_in[22];
    const float* gat1_bi  = (const float*)d_in[23];
    const float* bn3_g    = (const float*)d_in[24];
    const float* bn3_b    = (const float*)d_in[25];
    const float* bn3_m    = (const float*)d_in[26];
    const float* bn3_v    = (const float*)d_in[27];
    const float* fin_w1   = (const float*)d_in[28];
    const float* fin_b1   = (const float*)d_in[29];
    const float* fin_w2   = (const float*)d_in[30];
    const float* fin_b2   = (const float*)d_in[31];
    float* out = (float*)d_out;

    float *hp_rx, *hp_h1, *hp_h2, *hp_xw, *hp_h3, *hp_h4, *hp_wt;
    float *hp_sc1, *hp_sh1, *hp_sc2, *hp_sh2;
    cudaGetSymbolAddress((void**)&hp_rx, g_rx);
    cudaGetSymbolAddress((void**)&hp_h1, g_h1);
    cudaGetSymbolAddress((void**)&hp_h2, g_h2);
    cudaGetSymbolAddress((void**)&hp_xw, g_xw);
    cudaGetSymbolAddress((void**)&hp_h3, g_h3);
    cudaGetSymbolAddress((void**)&hp_h4, g_h4);
    cudaGetSymbolAddress((void**)&hp_wt, g_wt);
    cudaGetSymbolAddress((void**)&hp_sc1, g_sc1);
    cudaGetSymbolAddress((void**)&hp_sh1, g_sh1);
    cudaGetSymbolAddress((void**)&hp_sc2, g_sc2);
    cudaGetSymbolAddress((void**)&hp_sh2, g_sh2);

    // 1) per-call state + BN prep + CSR build + x rounding + graph starts
    zero_kernel<<<(NN + 255) / 256, 256>>>();
    prep_bn<<<1, 256>>>(mlp_b1, bn1_g, bn1_b, bn1_m, bn1_v,
                        mlp_b2, bn2_g, bn2_b, bn2_m, bn2_v);
    round_x<<<(NN * FF + 255) / 256, 256>>>(x);
    graph_starts<<<1, 256>>>(batch);
    hist_kernel<<<(EE + 255) / 256, 256>>>(ei, ew);
    scan_blocks<<<(NN + 511) / 512, 512>>>();
    scan_sums<<<1, 64>>>();
    scan_add<<<(NN + 255) / 256, 256>>>();
    scatter_kernel<<<(EE + 255) / 256, 256>>>(ei, ew);

    const int MB = (NN + 127) / 128;  // 157
    const int AGG_BLOCKS = (NN * 32 + 255) / 256;

    // 2) node MLP (tf32 mma.sync)
    transpose_k<<<dim3(D0 / 32, FF / 32), dim3(32, 8)>>>(mlp_w1, hp_wt, FF, D0);
    tgemm<1><<<dim3(D0 / 128, MB), 256>>>(hp_rx, hp_wt, hp_h1, NN, D0, FF, hp_sc1, hp_sh1);
    transpose_k<<<dim3(D0 / 32, D0 / 32), dim3(32, 8)>>>(mlp_w2, hp_wt, D0, D0);
    tgemm<1><<<dim3(D0 / 128, MB), 256>>>(hp_h1, hp_wt, hp_h2, NN, D0, D0, hp_sc2, hp_sh2);

    // 3) GAT layer 0
    transpose_k<<<dim3(D1 / 32, D0 / 32), dim3(32, 8)>>>(gat0_w, hp_wt, D0, D1);
    tgemm<0><<<dim3(D1 / 128, MB), 256>>>(hp_h2, hp_wt, hp_xw, NN, D1, D0, nullptr, nullptr);
    logits_kernel<<<(NN * HH * 32 + 255) / 256, 256>>>(hp_xw, gat0_as, gat0_ad);
    gat_agg<1><<<AGG_BLOCKS, 256>>>(hp_xw, gat0_bi, hp_h3);

    // 4) GAT layer 1
    transpose_k<<<dim3(D1 / 32, D1 / 32), dim3(32, 8)>>>(gat1_w, hp_wt, D1, D1);
    tgemm<0><<<dim3(D1 / 128, MB), 256>>>(hp_h3, hp_wt, hp_xw, NN, D1, D1, nullptr, nullptr);
    logits_kernel<<<(NN * HH * 32 + 255) / 256, 256>>>(hp_xw, gat1_as, gat1_ad);
    gat_agg<0><<<AGG_BLOCKS, 256>>>(hp_xw, gat1_bi, hp_h4);

    // 5) pool + final head
    pool_kernel<<<GG, 256>>>(hp_h4);
    final_head<<<GG, 512>>>(bn3_g, bn3_b, bn3_m, bn3_v,
                            fin_w1, fin_b1, fin_w2, fin_b2, out);
}

// round 5
// speedup vs baseline: 2.2266x; 1.1490x over previous
#include <cuda_runtime.h>
#include <cstdint>

#define NN 20000
#define EE 320000
#define FF 128
#define D0 256
#define D1 512
#define HH 2
#define CC 256
#define GG 128
#define NC 10

// ---------------- scratch (device globals) ----------------
__device__ float g_rx[NN * FF];
__device__ float g_h1[NN * D0];
__device__ float g_h2[NN * D0];
__device__ float g_xw[NN * D1];
__device__ float g_h3[NN * D1];
__device__ float g_h4[NN * D1];
__device__ float g_wt0[FF * D0];
__device__ float g_wt1[D0 * D0];
__device__ float g_wt2[D0 * D1];
__device__ float g_wt3[D1 * D1];
__device__ float g_ls0[NN * HH], g_ld0[NN * HH];
__device__ float g_ls1[NN * HH], g_ld1[NN * HH];
__device__ int   g_deg[NN];
__device__ int   g_off[NN + 1];
__device__ int   g_cur[NN];
__device__ int   g_csr[EE];
__device__ int   g_bsum[64];
__device__ int   g_goff[GG + 1];
__device__ float g_sc1[D0], g_sh1[D0], g_sc2[D0], g_sh2[D0];

// ---------------- small helpers ----------------
__device__ __forceinline__ float rtf32(float x) {
    uint32_t u;
    asm("cvt.rna.tf32.f32 %0, %1;" : "=r"(u) : "f"(x));
    return __uint_as_float(u);
}
__device__ __forceinline__ uint32_t smem_u32(const void* p) {
    uint32_t a;
    asm("{ .reg .u64 t; cvta.to.shared.u64 t, %1; cvt.u32.u64 %0, t; }" : "=r"(a) : "l"(p));
    return a;
}
__device__ __forceinline__ void cpa16(uint32_t dst, const void* src, int sz) {
    asm volatile("cp.async.ca.shared.global [%0], [%1], 16, %2;"
                 :: "r"(dst), "l"(src), "r"(sz));
}
__device__ __forceinline__ void cp_commit() {
    asm volatile("cp.async.commit_group;");
}
template <int N>
__device__ __forceinline__ void cp_wait() {
    asm volatile("cp.async.wait_group %0;" :: "n"(N));
}
__device__ __forceinline__ void mma_tf32(float* d, const float* a, const float* b) {
    asm volatile(
        "mma.sync.aligned.m16n8k8.row.col.f32.tf32.tf32.f32 "
        "{%0,%1,%2,%3}, {%4,%5,%6,%7}, {%8,%9}, {%0,%1,%2,%3};"
        : "+f"(d[0]), "+f"(d[1]), "+f"(d[2]), "+f"(d[3])
        : "r"(__float_as_uint(a[0])), "r"(__float_as_uint(a[1])),
          "r"(__float_as_uint(a[2])), "r"(__float_as_uint(a[3])),
          "r"(__float_as_uint(b[0])), "r"(__float_as_uint(b[1])));
}

// ---------------- fused prepass: round x, zero state, graph bounds, BN fold ----------------
__global__ void fused_pre(const float* __restrict__ x, const int* __restrict__ batch,
                          const float* lb1, const float* g1, const float* b1,
                          const float* m1, const float* v1,
                          const float* lb2, const float* g2, const float* b2,
                          const float* m2, const float* v2) {
    int i = blockIdx.x * blockDim.x + threadIdx.x;
    if (i < NN * FF) g_rx[i] = rtf32(x[i]);
    if (i < NN * HH) { g_ls0[i] = 0.f; g_ld0[i] = 0.f; g_ls1[i] = 0.f; g_ld1[i] = 0.f; }
    if (i < NN) {
        g_deg[i] = 0;
        if (i == 0) {
            int c = batch[0];
            for (int g = 0; g <= c; g++) g_goff[g] = 0;
        } else {
            int p = batch[i - 1], c = batch[i];
            for (int g = p + 1; g <= c; g++) g_goff[g] = i;
        }
        if (i == NN - 1) {
            int c = batch[NN - 1];
            for (int g = c + 1; g <= GG; g++) g_goff[g] = NN;
        }
    }
    if (blockIdx.x == 0 && threadIdx.x < D0) {
        int t = threadIdx.x;
        float sc = g1[t] * rsqrtf(v1[t] + 1e-5f);
        g_sc1[t] = sc;
        g_sh1[t] = (lb1[t] - m1[t]) * sc + b1[t];
        float sc2 = g2[t] * rsqrtf(v2[t] + 1e-5f);
        g_sc2[t] = sc2;
        g_sh2[t] = (lb2[t] - m2[t]) * sc2 + b2[t];
    }
}

// ---------------- merged weight transposes (tf32-rounded), 4 matrices in 1 launch ----------------
__global__ void transpose_all(const float* __restrict__ w0, const float* __restrict__ w1,
                              const float* __restrict__ w2, const float* __restrict__ w3) {
    __shared__ float t[32][33];
    int b = blockIdx.x;
    const float* W; float* Wt; int K, N, bx, by;
    if (b < 32)       { W = w0; Wt = g_wt0; K = FF; N = D0; b -= 0;   bx = b % 8;  by = b / 8; }
    else if (b < 96)  { W = w1; Wt = g_wt1; K = D0; N = D0; b -= 32;  bx = b % 8;  by = b / 8; }
    else if (b < 224) { W = w2; Wt = g_wt2; K = D0; N = D1; b -= 96;  bx = b % 16; by = b / 16; }
    else              { W = w3; Wt = g_wt3; K = D1; N = D1; b -= 224; bx = b % 16; by = b / 16; }
    int x = threadIdx.x, y = threadIdx.y;
    int cx = bx * 32, cy = by * 32;
#pragma unroll
    for (int i = 0; i < 32; i += 8)
        t[y + i][x] = W[(size_t)(cy + y + i) * N + cx + x];
    __syncthreads();
#pragma unroll
    for (int i = 0; i < 32; i += 8)
        Wt[(size_t)(cx + y + i) * K + cy + x] = rtf32(t[x][y + i]);
}

// ---------------- tf32 mma.sync GEMM, 3-stage cp.async ----------------
// EPI 0: plain. EPI 1: rtf32(relu(acc*scale+shift)). EPI 2: plain store + fused
// attention-logit partials into lsb/ldb via atomics (asrc/adst indexed by global col).
#define TG_STAGES 3
#define TG_LDS 20
#define TG_SMEM (TG_STAGES * 2 * 128 * TG_LDS * 4)

template <int EPI>
__global__ void __launch_bounds__(256, 2) tgemm(
    const float* __restrict__ A, const float* __restrict__ Bt,
    float* __restrict__ Cm, int M, int Nn, int K,
    const float* __restrict__ scale, const float* __restrict__ shift,
    const float* __restrict__ asrc, const float* __restrict__ adst,
    float* __restrict__ lsb, float* __restrict__ ldb)
{
    extern __shared__ float smem[];
    // layout: [stage][A(128*20) | B(128*20)]
    const int tid = threadIdx.x;
    const int wid = tid >> 5, lane = tid & 31;
    const int wm = wid & 3, wn = wid >> 2;
    const int lr = lane >> 2, lc = lane & 3;
    const int m0 = blockIdx.y * 128, n0 = blockIdx.x * 128;

    const int arow0 = tid >> 1;
    const int ac4 = (tid & 1) * 2;
    uint32_t sbase = smem_u32(smem);

    float acc[2][8][4];
#pragma unroll
    for (int i = 0; i < 2; i++)
#pragma unroll
        for (int j = 0; j < 8; j++)
#pragma unroll
            for (int q = 0; q < 4; q++) acc[i][j][q] = 0.f;

    const int nch = K >> 4;

    auto load_chunk = [&](int ch, int st) {
        int k0 = ch << 4;
        uint32_t sA = sbase + (uint32_t)(st * 2 * 128 * TG_LDS) * 4u;
        uint32_t sB = sA + (uint32_t)(128 * TG_LDS) * 4u;
#pragma unroll
        for (int i = 0; i < 2; i++) {
            int row = arow0;
            int c4 = ac4 + i;
            int gr = m0 + row;
            int ok = (gr < M) ? 16 : 0;
            int grc = (gr < M) ? gr : (M - 1);
            cpa16(sA + (uint32_t)(row * TG_LDS + c4 * 4) * 4u,
                  A + (size_t)grc * K + k0 + c4 * 4, ok);
            cpa16(sB + (uint32_t)(row * TG_LDS + c4 * 4) * 4u,
                  Bt + (size_t)(n0 + row) * K + k0 + c4 * 4, 16);
        }
        cp_commit();
    };

    load_chunk(0, 0);
    load_chunk(1, 1);

    for (int ch = 0; ch < nch; ch++) {
        int st = ch % TG_STAGES;
        cp_wait<TG_STAGES - 2>();
        __syncthreads();
        if (ch + 2 < nch) load_chunk(ch + 2, (ch + 2) % TG_STAGES);

        const float* Ab = smem + st * 2 * 128 * TG_LDS + (wm * 32 + lr) * TG_LDS + lc;
        const float* Bb = smem + st * 2 * 128 * TG_LDS + 128 * TG_LDS + (wn * 64 + lr) * TG_LDS + lc;
#pragma unroll
        for (int ks = 0; ks < 2; ks++) {
            int k0 = ks * 8;
            float a[2][4], b[8][2];
#pragma unroll
            for (int mt = 0; mt < 2; mt++) {
                a[mt][0] = Ab[(mt * 16) * TG_LDS + k0];
                a[mt][1] = Ab[(mt * 16 + 8) * TG_LDS + k0];
                a[mt][2] = Ab[(mt * 16) * TG_LDS + k0 + 4];
                a[mt][3] = Ab[(mt * 16 + 8) * TG_LDS + k0 + 4];
            }
#pragma unroll
            for (int nt = 0; nt < 8; nt++) {
                b[nt][0] = Bb[(nt * 8) * TG_LDS + k0];
                b[nt][1] = Bb[(nt * 8) * TG_LDS + k0 + 4];
            }
#pragma unroll
            for (int mt = 0; mt < 2; mt++)
#pragma unroll
                for (int nt = 0; nt < 8; nt++)
                    mma_tf32(acc[mt][nt], a[mt], b[nt]);
        }
    }

    // ---- epilogue ----
    float sr[2][2] = {{0.f, 0.f}, {0.f, 0.f}};
    float dr[2][2] = {{0.f, 0.f}, {0.f, 0.f}};
#pragma unroll
    for (int mt = 0; mt < 2; mt++) {
        int row0 = m0 + wm * 32 + mt * 16 + lr;
#pragma unroll
        for (int nt = 0; nt < 8; nt++) {
            int col = n0 + wn * 64 + nt * 8 + lc * 2;
            float v0 = acc[mt][nt][0], v1 = acc[mt][nt][1];
            float v2 = acc[mt][nt][2], v3 = acc[mt][nt][3];
            if (EPI == 1) {
                float s0 = scale[col], s1 = scale[col + 1];
                float h0 = shift[col], h1 = shift[col + 1];
                v0 = rtf32(fmaxf(v0 * s0 + h0, 0.f));
                v1 = rtf32(fmaxf(v1 * s1 + h1, 0.f));
                v2 = rtf32(fmaxf(v2 * s0 + h0, 0.f));
                v3 = rtf32(fmaxf(v3 * s1 + h1, 0.f));
            }
            if (EPI == 2) {
                float as0 = asrc[col], as1 = asrc[col + 1];
                float ad0 = adst[col], ad1 = adst[col + 1];
                sr[mt][0] += v0 * as0 + v1 * as1;
                dr[mt][0] += v0 * ad0 + v1 * ad1;
                sr[mt][1] += v2 * as0 + v3 * as1;
                dr[mt][1] += v2 * ad0 + v3 * ad1;
            }
            if (row0 < M)
                *(float2*)(Cm + (size_t)row0 * Nn + col) = make_float2(v0, v1);
            if (row0 + 8 < M)
                *(float2*)(Cm + (size_t)(row0 + 8) * Nn + col) = make_float2(v2, v3);
        }
    }
    if (EPI == 2) {
        int h = (n0 >= 256) ? 1 : 0;
#pragma unroll
        for (int mt = 0; mt < 2; mt++)
#pragma unroll
            for (int half = 0; half < 2; half++) {
                float s = sr[mt][half], d = dr[mt][half];
                s += __shfl_xor_sync(0xffffffffu, s, 1);
                s += __shfl_xor_sync(0xffffffffu, s, 2);
                d += __shfl_xor_sync(0xffffffffu, d, 1);
                d += __shfl_xor_sync(0xffffffffu, d, 2);
                int row = m0 + wm * 32 + mt * 16 + lr + half * 8;
                if (lc == 0 && row < M) {
                    atomicAdd(&lsb[row * 2 + h], s);
                    atomicAdd(&ldb[row * 2 + h], d);
                }
            }
    }
}

// ---------------- CSR build ----------------
__global__ void hist_kernel(const int* __restrict__ ei, const int* __restrict__ ew) {
    int e = blockIdx.x * blockDim.x + threadIdx.x;
    if (e < EE && ew[e] == 1) atomicAdd(&g_deg[ei[EE + e]], 1);
}

__global__ void scan_blocks() {
    __shared__ int s[512];
    int tid = threadIdx.x;
    int i = blockIdx.x * 512 + tid;
    int v = (i < NN) ? g_deg[i] : 0;
    s[tid] = v;
    __syncthreads();
    for (int off = 1; off < 512; off <<= 1) {
        int u = (tid >= off) ? s[tid - off] : 0;
        __syncthreads();
        s[tid] += u;
        __syncthreads();
    }
    if (i < NN) g_off[i] = s[tid] - v;
    if (tid == 511) g_bsum[blockIdx.x] = s[511];
}

// adds block-prefix of bsum; also sets g_off[NN]
__global__ void scan_add2() {
    __shared__ int base;
    int i = blockIdx.x * blockDim.x + threadIdx.x;
    int sb = (int)((blockIdx.x * blockDim.x) >> 9);  // 512-block index (constant per block)
    if (threadIdx.x == 0) {
        int a = 0;
        for (int b = 0; b < sb; b++) a += g_bsum[b];
        base = a;
        if (blockIdx.x == 0) {
            int tot = 0;
            int nblk = (NN + 511) / 512;
            for (int b = 0; b < nblk; b++) tot += g_bsum[b];
            g_off[NN] = tot;
        }
    }
    __syncthreads();
    if (i < NN) {
        int v = g_off[i] + base;
        g_off[i] = v;
        g_cur[i] = v;
    }
}

__global__ void scatter_kernel(const int* __restrict__ ei, const int* __restrict__ ew) {
    int e = blockIdx.x * blockDim.x + threadIdx.x;
    if (e < EE && ew[e] == 1) {
        int d = ei[EE + e];
        int pos = atomicAdd(&g_cur[d], 1);
        g_csr[pos] = ei[e];
    }
}

// ---------------- GAT aggregation: one WARP per destination node ----------------
template <int ROUND>
__global__ void __launch_bounds__(256) gat_agg(const float* __restrict__ xw,
                                               const float* __restrict__ bias,
                                               float* __restrict__ out,
                                               const float* __restrict__ lsb,
                                               const float* __restrict__ ldb) {
    int gw = (blockIdx.x * blockDim.x + threadIdx.x) >> 5;
    if (gw >= NN) return;
    int lane = threadIdx.x & 31;
    int n = gw;
    int beg = g_off[n], end = g_off[n + 1];
    int deg = end - beg;
    float ld0 = ldb[n * 2], ld1 = ldb[n * 2 + 1];

    float m0 = -1e30f, m1 = -1e30f;
    for (int i = lane; i < deg; i += 32) {
        int s = g_csr[beg + i];
        float e0 = lsb[s * 2] + ld0;     e0 = e0 > 0.f ? e0 : 0.2f * e0;
        float e1 = lsb[s * 2 + 1] + ld1; e1 = e1 > 0.f ? e1 : 0.2f * e1;
        m0 = fmaxf(m0, e0);
        m1 = fmaxf(m1, e1);
    }
#pragma unroll
    for (int o = 16; o; o >>= 1) {
        m0 = fmaxf(m0, __shfl_xor_sync(0xffffffffu, m0, o));
        m1 = fmaxf(m1, __shfl_xor_sync(0xffffffffu, m1, o));
    }

    float4 a0 = make_float4(0.f, 0.f, 0.f, 0.f);
    float4 a1 = a0, a2 = a0, a3 = a0;
    float den0 = 0.f, den1 = 0.f;
    for (int base = 0; base < deg; base += 32) {
        int i = base + lane;
        float p0 = 0.f, p1 = 0.f;
        int sl = 0;
        if (i < deg) {
            sl = g_csr[beg + i];
            float e0 = lsb[sl * 2] + ld0;     e0 = e0 > 0.f ? e0 : 0.2f * e0;
            float e1 = lsb[sl * 2 + 1] + ld1; e1 = e1 > 0.f ? e1 : 0.2f * e1;
            p0 = __expf(e0 - m0);
            p1 = __expf(e1 - m1);
        }
        den0 += p0; den1 += p1;
        int cnt = min(32, deg - base);
        for (int j = 0; j < cnt; j++) {
            int s = __shfl_sync(0xffffffffu, sl, j);
            float q0 = __shfl_sync(0xffffffffu, p0, j);
            float q1 = __shfl_sync(0xffffffffu, p1, j);
            const float4* row = (const float4*)(xw + (size_t)s * D1);
            float4 v0 = row[lane];
            float4 v1 = row[32 + lane];
            float4 v2 = row[64 + lane];
            float4 v3 = row[96 + lane];
            a0.x += q0 * v0.x; a0.y += q0 * v0.y; a0.z += q0 * v0.z; a0.w += q0 * v0.w;
            a1.x += q0 * v1.x; a1.y += q0 * v1.y; a1.z += q0 * v1.z; a1.w += q0 * v1.w;
            a2.x += q1 * v2.x; a2.y += q1 * v2.y; a2.z += q1 * v2.z; a2.w += q1 * v2.w;
            a3.x += q1 * v3.x; a3.y += q1 * v3.y; a3.z += q1 * v3.z; a3.w += q1 * v3.w;
        }
    }
#pragma unroll
    for (int o = 16; o; o >>= 1) {
        den0 += __shfl_xor_sync(0xffffffffu, den0, o);
        den1 += __shfl_xor_sync(0xffffffffu, den1, o);
    }
    float r0 = 1.f / (den0 + 1e-16f), r1 = 1.f / (den1 + 1e-16f);

    const float4* bi = (const float4*)bias;
    float4* op = (float4*)(out + (size_t)n * D1);
    float4 b0 = bi[lane], b1 = bi[32 + lane], b2 = bi[64 + lane], b3 = bi[96 + lane];
    float4 o0 = make_float4(a0.x * r0 + b0.x, a0.y * r0 + b0.y, a0.z * r0 + b0.z, a0.w * r0 + b0.w);
    float4 o1 = make_float4(a1.x * r0 + b1.x, a1.y * r0 + b1.y, a1.z * r0 + b1.z, a1.w * r0 + b1.w);
    float4 o2 = make_float4(a2.x * r1 + b2.x, a2.y * r1 + b2.y, a2.z * r1 + b2.z, a2.w * r1 + b2.w);
    float4 o3 = make_float4(a3.x * r1 + b3.x, a3.y * r1 + b3.y, a3.z * r1 + b3.z, a3.w * r1 + b3.w);
    if (ROUND) {
        o0 = make_float4(rtf32(o0.x), rtf32(o0.y), rtf32(o0.z), rtf32(o0.w));
        o1 = make_float4(rtf32(o1.x), rtf32(o1.y), rtf32(o1.z), rtf32(o1.w));
        o2 = make_float4(rtf32(o2.x), rtf32(o2.y), rtf32(o2.z), rtf32(o2.w));
        o3 = make_float4(rtf32(o3.x), rtf32(o3.y), rtf32(o3.z), rtf32(o3.w));
    }
    op[lane] = o0;
    op[32 + lane] = o1;
    op[64 + lane] = o2;
    op[96 + lane] = o3;
}

// ---------------- final head (includes pooling) ----------------
__global__ void __launch_bounds__(512) final_head(
    const float* __restrict__ h,
    const float* __restrict__ bn3g, const float* __restrict__ bn3b,
    const float* __restrict__ bn3m, const float* __restrict__ bn3v,
    const float* __restrict__ w1, const float* __restrict__ b1,
    const float* __restrict__ w2, const float* __restrict__ b2,
    float* __restrict__ out)
{
    int g = blockIdx.x, t = threadIdx.x;
    __shared__ float z[512];
    __shared__ float s1[512];
    int s = g_goff[g], e = g_goff[g + 1];
    float a0 = 0.f, a1 = 0.f, a2 = 0.f, a3 = 0.f;
    int n = s;
    for (; n + 3 < e; n += 4) {
        a0 += h[(size_t)n * D1 + t];
        a1 += h[(size_t)(n + 1) * D1 + t];
        a2 += h[(size_t)(n + 2) * D1 + t];
        a3 += h[(size_t)(n + 3) * D1 + t];
    }
    for (; n < e; n++) a0 += h[(size_t)n * D1 + t];
    float pv = (a0 + a1 + a2 + a3) / fmaxf((float)(e - s), 1.0f);
    float sc = bn3g[t] * rsqrtf(bn3v[t] + 1e-5f);
    z[t] = fmaxf((pv - bn3m[t]) * sc + bn3b[t], 0.f);
    __syncthreads();
    float a = 0.f;
    for (int k = 0; k < 512; k++) a += z[k] * w1[(size_t)k * 512 + t];
    s1[t] = fmaxf(a + b1[t], 0.f);
    __syncthreads();
    if (t < NC * 32) {
        int col = t >> 5, lane = t & 31;
        float sv = 0.f;
        for (int k = lane; k < 512; k += 32) sv += s1[k] * w2[k * NC + col];
#pragma unroll
        for (int o = 16; o; o >>= 1) sv += __shfl_xor_sync(0xffffffffu, sv, o);
        if (!lane) out[g * NC + col] = sv + b2[col];
    }
}

// ---------------- host launcher ----------------
extern "C" void kernel_launch(void* const* d_in, const int* in_sizes, int n_in,
                              void* d_out, int out_size) {
    const float* x        = (const float*)d_in[0];
    const int*   ei       = (const int*)d_in[1];
    const int*   ew       = (const int*)d_in[2];
    const int*   batch    = (const int*)d_in[3];
    const float* mlp_w1   = (const float*)d_in[4];
    const float* mlp_b1   = (const float*)d_in[5];
    const float* bn1_g    = (const float*)d_in[6];
    const float* bn1_b    = (const float*)d_in[7];
    const float* bn1_m    = (const float*)d_in[8];
    const float* bn1_v    = (const float*)d_in[9];
    const float* mlp_w2   = (const float*)d_in[10];
    const float* mlp_b2   = (const float*)d_in[11];
    const float* bn2_g    = (const float*)d_in[12];
    const float* bn2_b    = (const float*)d_in[13];
    const float* bn2_m    = (const float*)d_in[14];
    const float* bn2_v    = (const float*)d_in[15];
    const float* gat0_w   = (const float*)d_in[16];
    const float* gat0_as  = (const float*)d_in[17];
    const float* gat0_ad  = (const float*)d_in[18];
    const float* gat0_bi  = (const float*)d_in[19];
    const float* gat1_w   = (const float*)d_in[20];
    const float* gat1_as  = (const float*)d_in[21];
    const float* gat1_ad  = (const float*)d_in[22];
    const float* gat1_bi  = (const float*)d_in[23];
    const float* bn3_g    = (const float*)d_in[24];
    const float* bn3_b    = (const float*)d_in[25];
    const float* bn3_m    = (const float*)d_in[26];
    const float* bn3_v    = (const float*)d_in[27];
    const float* fin_w1   = (const float*)d_in[28];
    const float* fin_b1   = (const float*)d_in[29];
    const float* fin_w2   = (const float*)d_in[30];
    const float* fin_b2   = (const float*)d_in[31];
    float* out = (float*)d_out;

    float *hp_rx, *hp_h1, *hp_h2, *hp_xw, *hp_h3, *hp_h4;
    float *hp_wt0, *hp_wt1, *hp_wt2, *hp_wt3;
    float *hp_sc1, *hp_sh1, *hp_sc2, *hp_sh2;
    float *hp_ls0, *hp_ld0, *hp_ls1, *hp_ld1;
    cudaGetSymbolAddress((void**)&hp_rx, g_rx);
    cudaGetSymbolAddress((void**)&hp_h1, g_h1);
    cudaGetSymbolAddress((void**)&hp_h2, g_h2);
    cudaGetSymbolAddress((void**)&hp_xw, g_xw);
    cudaGetSymbolAddress((void**)&hp_h3, g_h3);
    cudaGetSymbolAddress((void**)&hp_h4, g_h4);
    cudaGetSymbolAddress((void**)&hp_wt0, g_wt0);
    cudaGetSymbolAddress((void**)&hp_wt1, g_wt1);
    cudaGetSymbolAddress((void**)&hp_wt2, g_wt2);
    cudaGetSymbolAddress((void**)&hp_wt3, g_wt3);
    cudaGetSymbolAddress((void**)&hp_sc1, g_sc1);
    cudaGetSymbolAddress((void**)&hp_sh1, g_sh1);
    cudaGetSymbolAddress((void**)&hp_sc2, g_sc2);
    cudaGetSymbolAddress((void**)&hp_sh2, g_sh2);
    cudaGetSymbolAddress((void**)&hp_ls0, g_ls0);
    cudaGetSymbolAddress((void**)&hp_ld0, g_ld0);
    cudaGetSymbolAddress((void**)&hp_ls1, g_ls1);
    cudaGetSymbolAddress((void**)&hp_ld1, g_ld1);

    cudaFuncSetAttribute(tgemm<0>, cudaFuncAttributeMaxDynamicSharedMemorySize, TG_SMEM);
    cudaFuncSetAttribute(tgemm<1>, cudaFuncAttributeMaxDynamicSharedMemorySize, TG_SMEM);
    cudaFuncSetAttribute(tgemm<2>, cudaFuncAttributeMaxDynamicSharedMemorySize, TG_SMEM);

    // 1) prepass + CSR build + weight transposes
    fused_pre<<<(NN * FF + 255) / 256, 256>>>(x, batch,
        mlp_b1, bn1_g, bn1_b, bn1_m, bn1_v,
        mlp_b2, bn2_g, bn2_b, bn2_m, bn2_v);
    hist_kernel<<<(EE + 255) / 256, 256>>>(ei, ew);
    scan_blocks<<<(NN + 511) / 512, 512>>>();
    scan_add2<<<(NN + 255) / 256, 256>>>();
    scatter_kernel<<<(EE + 255) / 256, 256>>>(ei, ew);
    transpose_all<<<480, dim3(32, 8)>>>(mlp_w1, mlp_w2, gat0_w, gat1_w);

    const int MB = (NN + 127) / 128;  // 157
    const int AGG_BLOCKS = (NN * 32 + 255) / 256;

    // 2) node MLP
    tgemm<1><<<dim3(D0 / 128, MB), 256, TG_SMEM>>>(hp_rx, hp_wt0, hp_h1, NN, D0, FF,
        hp_sc1, hp_sh1, nullptr, nullptr, nullptr, nullptr);
    tgemm<1><<<dim3(D0 / 128, MB), 256, TG_SMEM>>>(hp_h1, hp_wt1, hp_h2, NN, D0, D0,
        hp_sc2, hp_sh2, nullptr, nullptr, nullptr, nullptr);

    // 3) GAT layer 0 (logits fused into GEMM epilogue)
    tgemm<2><<<dim3(D1 / 128, MB), 256, TG_SMEM>>>(hp_h2, hp_wt2, hp_xw, NN, D1, D0,
        nullptr, nullptr, gat0_as, gat0_ad, hp_ls0, hp_ld0);
    gat_agg<1><<<AGG_BLOCKS, 256>>>(hp_xw, gat0_bi, hp_h3, hp_ls0, hp_ld0);

    // 4) GAT layer 1
    tgemm<2><<<dim3(D1 / 128, MB), 256, TG_SMEM>>>(hp_h3, hp_wt3, hp_xw, NN, D1, D1,
        nullptr, nullptr, gat1_as, gat1_ad, hp_ls1, hp_ld1);
    gat_agg<0><<<AGG_BLOCKS, 256>>>(hp_xw, gat1_bi, hp_h4, hp_ls1, hp_ld1);

    // 5) pooled final head
    final_head<<<GG, 512>>>(hp_h4, bn3_g, bn3_b, bn3_m, bn3_v,
                            fin_w1, fin_b1, fin_w2, fin_b2, out);
}

// round 6
// speedup vs baseline: 2.3931x; 1.0748x over previous
#include <cuda_runtime.h>
#include <cstdint>

#define NN 20000
#define EE 320000
#define FF 128
#define D0 256
#define D1 512
#define HH 2
#define CC 256
#define GG 128
#define NC 10

// ---------------- scratch (device globals; zero-initialized at load) ----------------
__device__ float g_rx[NN * FF];
__device__ float g_h1[NN * D0];
__device__ float g_h2[NN * D0];
__device__ float g_xw[NN * D1];
__device__ float g_h3[NN * D1];
__device__ float g_h4[NN * D1];
__device__ float g_wt0[FF * D0];
__device__ float g_wt1[D0 * D0];
__device__ float g_wt2[D0 * D1];
__device__ float g_wt3[D1 * D1];
__device__ float g_ls0[NN * HH], g_ld0[NN * HH];
__device__ float g_ls1[NN * HH], g_ld1[NN * HH];
__device__ int   g_deg[NN];      // invariant: all-zero at kernel_launch entry
__device__ int   g_off[NN + 1];
__device__ int   g_cur[NN];
__device__ int   g_csr[EE];
__device__ int   g_bsum[64];
__device__ int   g_goff[GG + 1];
__device__ float g_sc1[D0], g_sh1[D0], g_sc2[D0], g_sh2[D0];

// ---------------- small helpers ----------------
__device__ __forceinline__ float rtf32(float x) {
    uint32_t u;
    asm("cvt.rna.tf32.f32 %0, %1;" : "=r"(u) : "f"(x));
    return __uint_as_float(u);
}
__device__ __forceinline__ uint32_t smem_u32(const void* p) {
    uint32_t a;
    asm("{ .reg .u64 t; cvta.to.shared.u64 t, %1; cvt.u32.u64 %0, t; }" : "=r"(a) : "l"(p));
    return a;
}
__device__ __forceinline__ void cpa16(uint32_t dst, const void* src, int sz) {
    asm volatile("cp.async.ca.shared.global [%0], [%1], 16, %2;"
                 :: "r"(dst), "l"(src), "r"(sz));
}
__device__ __forceinline__ void cp_commit() {
    asm volatile("cp.async.commit_group;");
}
template <int N>
__device__ __forceinline__ void cp_wait() {
    asm volatile("cp.async.wait_group %0;" :: "n"(N));
}
__device__ __forceinline__ void mma_tf32(float* d, const float* a, const float* b) {
    asm volatile(
        "mma.sync.aligned.m16n8k8.row.col.f32.tf32.tf32.f32 "
        "{%0,%1,%2,%3}, {%4,%5,%6,%7}, {%8,%9}, {%0,%1,%2,%3};"
        : "+f"(d[0]), "+f"(d[1]), "+f"(d[2]), "+f"(d[3])
        : "r"(__float_as_uint(a[0])), "r"(__float_as_uint(a[1])),
          "r"(__float_as_uint(a[2])), "r"(__float_as_uint(a[3])),
          "r"(__float_as_uint(b[0])), "r"(__float_as_uint(b[1])));
}

// ---------------- fused prepass: rx round + hist + logits zero + graph bounds
// ---------------- + BN fold + all 4 weight transposes ----------------
#define NB_RX ((NN * FF + 255) / 256)   // 10000
#define NB_TR 480

__global__ void fused_pre(const float* __restrict__ x, const int* __restrict__ batch,
                          const int* __restrict__ ei, const int* __restrict__ ew,
                          const float* lb1, const float* g1, const float* b1,
                          const float* m1, const float* v1,
                          const float* lb2, const float* g2, const float* b2,
                          const float* m2, const float* v2,
                          const float* __restrict__ w0, const float* __restrict__ w1,
                          const float* __restrict__ w2, const float* __restrict__ w3) {
    if (blockIdx.x >= NB_RX) {
        // ---- weight transpose part ----
        __shared__ float t[32][33];
        int b = blockIdx.x - NB_RX;
        const float* W; float* Wt; int K, N, bx, by;
        if (b < 32)       { W = w0; Wt = g_wt0; K = FF; N = D0; bx = b % 8;  by = b / 8; }
        else if (b < 96)  { W = w1; Wt = g_wt1; K = D0; N = D0; b -= 32;  bx = b % 8;  by = b / 8; }
        else if (b < 224) { W = w2; Wt = g_wt2; K = D0; N = D1; b -= 96;  bx = b % 16; by = b / 16; }
        else              { W = w3; Wt = g_wt3; K = D1; N = D1; b -= 224; bx = b % 16; by = b / 16; }
        int xx = threadIdx.x & 31, yy = threadIdx.x >> 5;
        int cx = bx * 32, cy = by * 32;
#pragma unroll
        for (int i = 0; i < 32; i += 8)
            t[yy + i][xx] = W[(size_t)(cy + yy + i) * N + cx + xx];
        __syncthreads();
#pragma unroll
        for (int i = 0; i < 32; i += 8)
            Wt[(size_t)(cx + yy + i) * K + cy + xx] = rtf32(t[xx][yy + i]);
        return;
    }
    int i = blockIdx.x * blockDim.x + threadIdx.x;
    if (i < NN * FF) g_rx[i] = rtf32(x[i]);
    if (i < NN * HH) { g_ls0[i] = 0.f; g_ld0[i] = 0.f; g_ls1[i] = 0.f; g_ld1[i] = 0.f; }
    if (i < EE && ew[i] == 1) atomicAdd(&g_deg[ei[EE + i]], 1);   // histogram
    if (i < NN) {
        if (i == 0) {
            int c = batch[0];
            for (int g = 0; g <= c; g++) g_goff[g] = 0;
        } else {
            int p = batch[i - 1], c = batch[i];
            for (int g = p + 1; g <= c; g++) g_goff[g] = i;
        }
        if (i == NN - 1) {
            int c = batch[NN - 1];
            for (int g = c + 1; g <= GG; g++) g_goff[g] = NN;
        }
    }
    if (blockIdx.x == 0 && threadIdx.x < D0) {
        int t = threadIdx.x;
        float sc = g1[t] * rsqrtf(v1[t] + 1e-5f);
        g_sc1[t] = sc;
        g_sh1[t] = (lb1[t] - m1[t]) * sc + b1[t];
        float sc2 = g2[t] * rsqrtf(v2[t] + 1e-5f);
        g_sc2[t] = sc2;
        g_sh2[t] = (lb2[t] - m2[t]) * sc2 + b2[t];
    }
}

// ---------------- tf32 mma.sync GEMM, 4-stage cp.async ----------------
#define TG_STAGES 4
#define TG_LDS 20
#define TG_STAGE_FLOATS (2 * 128 * TG_LDS)
#define TG_SMEM (TG_STAGES * TG_STAGE_FLOATS * 4)

template <int EPI>
__global__ void __launch_bounds__(256, 2) tgemm(
    const float* __restrict__ A, const float* __restrict__ Bt,
    float* __restrict__ Cm, int M, int Nn, int K,
    const float* __restrict__ scale, const float* __restrict__ shift,
    const float* __restrict__ asrc, const float* __restrict__ adst,
    float* __restrict__ lsb, float* __restrict__ ldb)
{
    extern __shared__ float smem[];
    const int tid = threadIdx.x;
    const int wid = tid >> 5, lane = tid & 31;
    const int wm = wid & 3, wn = wid >> 2;
    const int lr = lane >> 2, lc = lane & 3;
    const int m0 = blockIdx.y * 128, n0 = blockIdx.x * 128;

    const int arow0 = tid >> 1;
    const int ac4 = (tid & 1) * 2;
    uint32_t sbase = smem_u32(smem);

    float acc[2][8][4];
#pragma unroll
    for (int i = 0; i < 2; i++)
#pragma unroll
        for (int j = 0; j < 8; j++)
#pragma unroll
            for (int q = 0; q < 4; q++) acc[i][j][q] = 0.f;

    const int nch = K >> 4;

    auto load_chunk = [&](int ch, int st) {
        int k0 = ch << 4;
        uint32_t sA = sbase + (uint32_t)(st * TG_STAGE_FLOATS) * 4u;
        uint32_t sB = sA + (uint32_t)(128 * TG_LDS) * 4u;
#pragma unroll
        for (int i = 0; i < 2; i++) {
            int row = arow0;
            int c4 = ac4 + i;
            int gr = m0 + row;
            int ok = (gr < M) ? 16 : 0;
            int grc = (gr < M) ? gr : (M - 1);
            cpa16(sA + (uint32_t)(row * TG_LDS + c4 * 4) * 4u,
                  A + (size_t)grc * K + k0 + c4 * 4, ok);
            cpa16(sB + (uint32_t)(row * TG_LDS + c4 * 4) * 4u,
                  Bt + (size_t)(n0 + row) * K + k0 + c4 * 4, 16);
        }
        cp_commit();
    };

    load_chunk(0, 0);
    if (nch > 1) load_chunk(1, 1);
    if (nch > 2) load_chunk(2, 2);

    for (int ch = 0; ch < nch; ch++) {
        int st = ch % TG_STAGES;
        cp_wait<TG_STAGES - 2>();
        __syncthreads();
        if (ch + 3 < nch) load_chunk(ch + 3, (ch + 3) % TG_STAGES);

        const float* Ab = smem + st * TG_STAGE_FLOATS + (wm * 32 + lr) * TG_LDS + lc;
        const float* Bb = smem + st * TG_STAGE_FLOATS + 128 * TG_LDS + (wn * 64 + lr) * TG_LDS + lc;
#pragma unroll
        for (int ks = 0; ks < 2; ks++) {
            int k0 = ks * 8;
            float a[2][4], b[8][2];
#pragma unroll
            for (int mt = 0; mt < 2; mt++) {
                a[mt][0] = Ab[(mt * 16) * TG_LDS + k0];
                a[mt][1] = Ab[(mt * 16 + 8) * TG_LDS + k0];
                a[mt][2] = Ab[(mt * 16) * TG_LDS + k0 + 4];
                a[mt][3] = Ab[(mt * 16 + 8) * TG_LDS + k0 + 4];
            }
#pragma unroll
            for (int nt = 0; nt < 8; nt++) {
                b[nt][0] = Bb[(nt * 8) * TG_LDS + k0];
                b[nt][1] = Bb[(nt * 8) * TG_LDS + k0 + 4];
            }
#pragma unroll
            for (int mt = 0; mt < 2; mt++)
#pragma unroll
                for (int nt = 0; nt < 8; nt++)
                    mma_tf32(acc[mt][nt], a[mt], b[nt]);
        }
    }

    // ---- epilogue ----
    float sr[2][2] = {{0.f, 0.f}, {0.f, 0.f}};
    float dr[2][2] = {{0.f, 0.f}, {0.f, 0.f}};
#pragma unroll
    for (int mt = 0; mt < 2; mt++) {
        int row0 = m0 + wm * 32 + mt * 16 + lr;
#pragma unroll
        for (int nt = 0; nt < 8; nt++) {
            int col = n0 + wn * 64 + nt * 8 + lc * 2;
            float v0 = acc[mt][nt][0], v1 = acc[mt][nt][1];
            float v2 = acc[mt][nt][2], v3 = acc[mt][nt][3];
            if (EPI == 1) {
                float s0 = scale[col], s1 = scale[col + 1];
                float h0 = shift[col], h1 = shift[col + 1];
                v0 = rtf32(fmaxf(v0 * s0 + h0, 0.f));
                v1 = rtf32(fmaxf(v1 * s1 + h1, 0.f));
                v2 = rtf32(fmaxf(v2 * s0 + h0, 0.f));
                v3 = rtf32(fmaxf(v3 * s1 + h1, 0.f));
            }
            if (EPI == 2) {
                float as0 = asrc[col], as1 = asrc[col + 1];
                float ad0 = adst[col], ad1 = adst[col + 1];
                sr[mt][0] += v0 * as0 + v1 * as1;
                dr[mt][0] += v0 * ad0 + v1 * ad1;
                sr[mt][1] += v2 * as0 + v3 * as1;
                dr[mt][1] += v2 * ad0 + v3 * ad1;
            }
            if (row0 < M)
                *(float2*)(Cm + (size_t)row0 * Nn + col) = make_float2(v0, v1);
            if (row0 + 8 < M)
                *(float2*)(Cm + (size_t)(row0 + 8) * Nn + col) = make_float2(v2, v3);
        }
    }
    if (EPI == 2) {
        int h = (n0 >= 256) ? 1 : 0;
#pragma unroll
        for (int mt = 0; mt < 2; mt++)
#pragma unroll
            for (int half = 0; half < 2; half++) {
                float s = sr[mt][half], d = dr[mt][half];
                s += __shfl_xor_sync(0xffffffffu, s, 1);
                s += __shfl_xor_sync(0xffffffffu, s, 2);
                d += __shfl_xor_sync(0xffffffffu, d, 1);
                d += __shfl_xor_sync(0xffffffffu, d, 2);
                int row = m0 + wm * 32 + mt * 16 + lr + half * 8;
                if (lc == 0 && row < M) {
                    atomicAdd(&lsb[row * 2 + h], s);
                    atomicAdd(&ldb[row * 2 + h], d);
                }
            }
    }
}

// ---------------- CSR build ----------------
__global__ void scan_blocks() {
    __shared__ int s[512];
    int tid = threadIdx.x;
    int i = blockIdx.x * 512 + tid;
    int v = (i < NN) ? g_deg[i] : 0;
    if (i < NN) g_deg[i] = 0;        // re-zero for next call (maintains invariant)
    s[tid] = v;
    __syncthreads();
    for (int off = 1; off < 512; off <<= 1) {
        int u = (tid >= off) ? s[tid - off] : 0;
        __syncthreads();
        s[tid] += u;
        __syncthreads();
    }
    if (i < NN) g_off[i] = s[tid] - v;
    if (tid == 511) g_bsum[blockIdx.x] = s[511];
}

__global__ void scan_add2() {
    __shared__ int base;
    int i = blockIdx.x * blockDim.x + threadIdx.x;
    int sb = (int)((blockIdx.x * blockDim.x) >> 9);
    if (threadIdx.x == 0) {
        int a = 0;
        for (int b = 0; b < sb; b++) a += g_bsum[b];
        base = a;
        if (blockIdx.x == 0) {
            int tot = 0;
            int nblk = (NN + 511) / 512;
            for (int b = 0; b < nblk; b++) tot += g_bsum[b];
            g_off[NN] = tot;
        }
    }
    __syncthreads();
    if (i < NN) {
        int v = g_off[i] + base;
        g_off[i] = v;
        g_cur[i] = v;
    }
}

__global__ void scatter_kernel(const int* __restrict__ ei, const int* __restrict__ ew) {
    int e = blockIdx.x * blockDim.x + threadIdx.x;
    if (e < EE && ew[e] == 1) {
        int d = ei[EE + e];
        int pos = atomicAdd(&g_cur[d], 1);
        g_csr[pos] = ei[e];
    }
}

// ---------------- GAT aggregation: one WARP per destination node ----------------
template <int ROUND>
__global__ void __launch_bounds__(256) gat_agg(const float* __restrict__ xw,
                                               const float* __restrict__ bias,
                                               float* __restrict__ out,
                                               const float* __restrict__ lsb,
                                               const float* __restrict__ ldb) {
    int gw = (blockIdx.x * blockDim.x + threadIdx.x) >> 5;
    if (gw >= NN) return;
    int lane = threadIdx.x & 31;
    int n = gw;
    int beg = g_off[n], end = g_off[n + 1];
    int deg = end - beg;
    float ld0 = ldb[n * 2], ld1 = ldb[n * 2 + 1];

    float4 a0 = make_float4(0.f, 0.f, 0.f, 0.f);
    float4 a1 = a0, a2 = a0, a3 = a0;
    float den0 = 0.f, den1 = 0.f;

    // helper macro for the weighted row accumulation of edge slot j
#define ACC_EDGE(SL, P0V, P1V, J)                                               \
    {                                                                           \
        int s_ = __shfl_sync(0xffffffffu, (SL), (J));                           \
        float q0_ = __shfl_sync(0xffffffffu, (P0V), (J));                       \
        float q1_ = __shfl_sync(0xffffffffu, (P1V), (J));                       \
        const float4* row_ = (const float4*)(xw + (size_t)s_ * D1);             \
        float4 v0_ = row_[lane];                                                \
        float4 v1_ = row_[32 + lane];                                           \
        float4 v2_ = row_[64 + lane];                                           \
        float4 v3_ = row_[96 + lane];                                           \
        a0.x += q0_ * v0_.x; a0.y += q0_ * v0_.y; a0.z += q0_ * v0_.z; a0.w += q0_ * v0_.w; \
        a1.x += q0_ * v1_.x; a1.y += q0_ * v1_.y; a1.z += q0_ * v1_.z; a1.w += q0_ * v1_.w; \
        a2.x += q1_ * v2_.x; a2.y += q1_ * v2_.y; a2.z += q1_ * v2_.z; a2.w += q1_ * v2_.w; \
        a3.x += q1_ * v3_.x; a3.y += q1_ * v3_.y; a3.z += q1_ * v3_.z; a3.w += q1_ * v3_.w; \
    }

    if (deg <= 32) {
        // ---- fast path: single chunk, one CSR read, logits in registers ----
        int sl = 0;
        float e0 = -1e30f, e1 = -1e30f;
        if (lane < deg) {
            sl = g_csr[beg + lane];
            e0 = lsb[sl * 2] + ld0;     e0 = e0 > 0.f ? e0 : 0.2f * e0;
            e1 = lsb[sl * 2 + 1] + ld1; e1 = e1 > 0.f ? e1 : 0.2f * e1;
        }
        float m0 = e0, m1 = e1;
#pragma unroll
        for (int o = 16; o; o >>= 1) {
            m0 = fmaxf(m0, __shfl_xor_sync(0xffffffffu, m0, o));
            m1 = fmaxf(m1, __shfl_xor_sync(0xffffffffu, m1, o));
        }
        float p0 = (lane < deg) ? __expf(e0 - m0) : 0.f;
        float p1 = (lane < deg) ? __expf(e1 - m1) : 0.f;
        den0 = p0; den1 = p1;
        int j = 0;
        for (; j + 1 < deg; j += 2) { ACC_EDGE(sl, p0, p1, j); ACC_EDGE(sl, p0, p1, j + 1); }
        if (j < deg) ACC_EDGE(sl, p0, p1, j);
    } else {
        // ---- general path ----
        float m0 = -1e30f, m1 = -1e30f;
        for (int i = lane; i < deg; i += 32) {
            int s = g_csr[beg + i];
            float e0 = lsb[s * 2] + ld0;     e0 = e0 > 0.f ? e0 : 0.2f * e0;
            float e1 = lsb[s * 2 + 1] + ld1; e1 = e1 > 0.f ? e1 : 0.2f * e1;
            m0 = fmaxf(m0, e0);
            m1 = fmaxf(m1, e1);
        }
#pragma unroll
        for (int o = 16; o; o >>= 1) {
            m0 = fmaxf(m0, __shfl_xor_sync(0xffffffffu, m0, o));
            m1 = fmaxf(m1, __shfl_xor_sync(0xffffffffu, m1, o));
        }
        for (int base = 0; base < deg; base += 32) {
            int i = base + lane;
            float p0 = 0.f, p1 = 0.f;
            int sl = 0;
            if (i < deg) {
                sl = g_csr[beg + i];
                float e0 = lsb[sl * 2] + ld0;     e0 = e0 > 0.f ? e0 : 0.2f * e0;
                float e1 = lsb[sl * 2 + 1] + ld1; e1 = e1 > 0.f ? e1 : 0.2f * e1;
                p0 = __expf(e0 - m0);
                p1 = __expf(e1 - m1);
            }
            den0 += p0; den1 += p1;
            int cnt = min(32, deg - base);
            int j = 0;
            for (; j + 1 < cnt; j += 2) { ACC_EDGE(sl, p0, p1, j); ACC_EDGE(sl, p0, p1, j + 1); }
            if (j < cnt) ACC_EDGE(sl, p0, p1, j);
        }
    }
#undef ACC_EDGE

#pragma unroll
    for (int o = 16; o; o >>= 1) {
        den0 += __shfl_xor_sync(0xffffffffu, den0, o);
        den1 += __shfl_xor_sync(0xffffffffu, den1, o);
    }
    float r0 = 1.f / (den0 + 1e-16f), r1 = 1.f / (den1 + 1e-16f);

    const float4* bi = (const float4*)bias;
    float4* op = (float4*)(out + (size_t)n * D1);
    float4 b0 = bi[lane], b1 = bi[32 + lane], b2 = bi[64 + lane], b3 = bi[96 + lane];
    float4 o0 = make_float4(a0.x * r0 + b0.x, a0.y * r0 + b0.y, a0.z * r0 + b0.z, a0.w * r0 + b0.w);
    float4 o1 = make_float4(a1.x * r0 + b1.x, a1.y * r0 + b1.y, a1.z * r0 + b1.z, a1.w * r0 + b1.w);
    float4 o2 = make_float4(a2.x * r1 + b2.x, a2.y * r1 + b2.y, a2.z * r1 + b2.z, a2.w * r1 + b2.w);
    float4 o3 = make_float4(a3.x * r1 + b3.x, a3.y * r1 + b3.y, a3.z * r1 + b3.z, a3.w * r1 + b3.w);
    if (ROUND) {
        o0 = make_float4(rtf32(o0.x), rtf32(o0.y), rtf32(o0.z), rtf32(o0.w));
        o1 = make_float4(rtf32(o1.x), rtf32(o1.y), rtf32(o1.z), rtf32(o1.w));
        o2 = make_float4(rtf32(o2.x), rtf32(o2.y), rtf32(o2.z), rtf32(o2.w));
        o3 = make_float4(rtf32(o3.x), rtf32(o3.y), rtf32(o3.z), rtf32(o3.w));
    }
    op[lane] = o0;
    op[32 + lane] = o1;
    op[64 + lane] = o2;
    op[96 + lane] = o3;
}

// ---------------- final head (includes pooling) ----------------
__global__ void __launch_bounds__(512) final_head(
    const float* __restrict__ h,
    const float* __restrict__ bn3g, const float* __restrict__ bn3b,
    const float* __restrict__ bn3m, const float* __restrict__ bn3v,
    const float* __restrict__ w1, const float* __restrict__ b1,
    const float* __restrict__ w2, const float* __restrict__ b2,
    float* __restrict__ out)
{
    int g = blockIdx.x, t = threadIdx.x;
    __shared__ float z[512];
    __shared__ float s1[512];
    int s = g_goff[g], e = g_goff[g + 1];
    float a0 = 0.f, a1 = 0.f, a2 = 0.f, a3 = 0.f;
    int n = s;
    for (; n + 3 < e; n += 4) {
        a0 += h[(size_t)n * D1 + t];
        a1 += h[(size_t)(n + 1) * D1 + t];
        a2 += h[(size_t)(n + 2) * D1 + t];
        a3 += h[(size_t)(n + 3) * D1 + t];
    }
    for (; n < e; n++) a0 += h[(size_t)n * D1 + t];
    float pv = (a0 + a1 + a2 + a3) / fmaxf((float)(e - s), 1.0f);
    float sc = bn3g[t] * rsqrtf(bn3v[t] + 1e-5f);
    z[t] = fmaxf((pv - bn3m[t]) * sc + bn3b[t], 0.f);
    __syncthreads();
    float a = 0.f;
    for (int k = 0; k < 512; k++) a += z[k] * w1[(size_t)k * 512 + t];
    s1[t] = fmaxf(a + b1[t], 0.f);
    __syncthreads();
    if (t < NC * 32) {
        int col = t >> 5, lane = t & 31;
        float sv = 0.f;
        for (int k = lane; k < 512; k += 32) sv += s1[k] * w2[k * NC + col];
#pragma unroll
        for (int o = 16; o; o >>= 1) sv += __shfl_xor_sync(0xffffffffu, sv, o);
        if (!lane) out[g * NC + col] = sv + b2[col];
    }
}

// ---------------- host launcher ----------------
extern "C" void kernel_launch(void* const* d_in, const int* in_sizes, int n_in,
                              void* d_out, int out_size) {
    const float* x        = (const float*)d_in[0];
    const int*   ei       = (const int*)d_in[1];
    const int*   ew       = (const int*)d_in[2];
    const int*   batch    = (const int*)d_in[3];
    const float* mlp_w1   = (const float*)d_in[4];
    const float* mlp_b1   = (const float*)d_in[5];
    const float* bn1_g    = (const float*)d_in[6];
    const float* bn1_b    = (const float*)d_in[7];
    const float* bn1_m    = (const float*)d_in[8];
    const float* bn1_v    = (const float*)d_in[9];
    const float* mlp_w2   = (const float*)d_in[10];
    const float* mlp_b2   = (const float*)d_in[11];
    const float* bn2_g    = (const float*)d_in[12];
    const float* bn2_b    = (const float*)d_in[13];
    const float* bn2_m    = (const float*)d_in[14];
    const float* bn2_v    = (const float*)d_in[15];
    const float* gat0_w   = (const float*)d_in[16];
    const float* gat0_as  = (const float*)d_in[17];
    const float* gat0_ad  = (const float*)d_in[18];
    const float* gat0_bi  = (const float*)d_in[19];
    const float* gat1_w   = (const float*)d_in[20];
    const float* gat1_as  = (const float*)d_in[21];
    const float* gat1_ad  = (const float*)d_in[22];
    const float* gat1_bi  = (const float*)d_in[23];
    const float* bn3_g    = (const float*)d_in[24];
    const float* bn3_b    = (const float*)d_in[25];
    const float* bn3_m    = (const float*)d_in[26];
    const float* bn3_v    = (const float*)d_in[27];
    const float* fin_w1   = (const float*)d_in[28];
    const float* fin_b1   = (const float*)d_in[29];
    const float* fin_w2   = (const float*)d_in[30];
    const float* fin_b2   = (const float*)d_in[31];
    float* out = (float*)d_out;

    float *hp_rx, *hp_h1, *hp_h2, *hp_xw, *hp_h3, *hp_h4;
    float *hp_wt0, *hp_wt1, *hp_wt2, *hp_wt3;
    float *hp_sc1, *hp_sh1, *hp_sc2, *hp_sh2;
    float *hp_ls0, *hp_ld0, *hp_ls1, *hp_ld1;
    cudaGetSymbolAddress((void**)&hp_rx, g_rx);
    cudaGetSymbolAddress((void**)&hp_h1, g_h1);
    cudaGetSymbolAddress((void**)&hp_h2, g_h2);
    cudaGetSymbolAddress((void**)&hp_xw, g_xw);
    cudaGetSymbolAddress((void**)&hp_h3, g_h3);
    cudaGetSymbolAddress((void**)&hp_h4, g_h4);
    cudaGetSymbolAddress((void**)&hp_wt0, g_wt0);
    cudaGetSymbolAddress((void**)&hp_wt1, g_wt1);
    cudaGetSymbolAddress((void**)&hp_wt2, g_wt2);
    cudaGetSymbolAddress((void**)&hp_wt3, g_wt3);
    cudaGetSymbolAddress((void**)&hp_sc1, g_sc1);
    cudaGetSymbolAddress((void**)&hp_sh1, g_sh1);
    cudaGetSymbolAddress((void**)&hp_sc2, g_sc2);
    cudaGetSymbolAddress((void**)&hp_sh2, g_sh2);
    cudaGetSymbolAddress((void**)&hp_ls0, g_ls0);
    cudaGetSymbolAddress((void**)&hp_ld0, g_ld0);
    cudaGetSymbolAddress((void**)&hp_ls1, g_ls1);
    cudaGetSymbolAddress((void**)&hp_ld1, g_ld1);

    cudaFuncSetAttribute(tgemm<0>, cudaFuncAttributeMaxDynamicSharedMemorySize, TG_SMEM);
    cudaFuncSetAttribute(tgemm<1>, cudaFuncAttributeMaxDynamicSharedMemorySize, TG_SMEM);
    cudaFuncSetAttribute(tgemm<2>, cudaFuncAttributeMaxDynamicSharedMemorySize, TG_SMEM);

    // 1) mega-prepass (rx + hist + zeros + graph bounds + BN fold + transposes) + CSR
    fused_pre<<<NB_RX + NB_TR, 256>>>(x, batch, ei, ew,
        mlp_b1, bn1_g, bn1_b, bn1_m, bn1_v,
        mlp_b2, bn2_g, bn2_b, bn2_m, bn2_v,
        mlp_w1, mlp_w2, gat0_w, gat1_w);
    scan_blocks<<<(NN + 511) / 512, 512>>>();
    scan_add2<<<(NN + 255) / 256, 256>>>();
    scatter_kernel<<<(EE + 255) / 256, 256>>>(ei, ew);

    const int MB = (NN + 127) / 128;  // 157
    const int AGG_BLOCKS = (NN * 32 + 255) / 256;

    // 2) node MLP
    tgemm<1><<<dim3(D0 / 128, MB), 256, TG_SMEM>>>(hp_rx, hp_wt0, hp_h1, NN, D0, FF,
        hp_sc1, hp_sh1, nullptr, nullptr, nullptr, nullptr);
    tgemm<1><<<dim3(D0 / 128, MB), 256, TG_SMEM>>>(hp_h1, hp_wt1, hp_h2, NN, D0, D0,
        hp_sc2, hp_sh2, nullptr, nullptr, nullptr, nullptr);

    // 3) GAT layer 0
    tgemm<2><<<dim3(D1 / 128, MB), 256, TG_SMEM>>>(hp_h2, hp_wt2, hp_xw, NN, D1, D0,
        nullptr, nullptr, gat0_as, gat0_ad, hp_ls0, hp_ld0);
    gat_agg<1><<<AGG_BLOCKS, 256>>>(hp_xw, gat0_bi, hp_h3, hp_ls0, hp_ld0);

    // 4) GAT layer 1
    tgemm<2><<<dim3(D1 / 128, MB), 256, TG_SMEM>>>(hp_h3, hp_wt3, hp_xw, NN, D1, D1,
        nullptr, nullptr, gat1_as, gat1_ad, hp_ls1, hp_ld1);
    gat_agg<0><<<AGG_BLOCKS, 256>>>(hp_xw, gat1_bi, hp_h4, hp_ls1, hp_ld1);

    // 5) pooled final head
    final_head<<<GG, 512>>>(hp_h4, bn3_g, bn3_b, bn3_m, bn3_v,
                            fin_w1, fin_b1, fin_w2, fin_b2, out);
}